// round 10
// baseline (speedup 1.0000x reference)
#include <cuda_runtime.h>
#include <cuda_bf16.h>
#include <cstdint>

#define N_NODES 50000
#define N_EDGES 600000
#define LATENT 128
#define IN_FEAT 7
#define STEPS 3

// -------- scratch (static device globals; no allocation) --------
__device__ float g_h [N_NODES * LATENT];
__device__ float g_x2[N_NODES * LATENT];
__device__ float g_inv_s[N_NODES];
__device__ int   g_cnt_s[N_NODES];
__device__ int   g_cnt_r[N_NODES];
__device__ int   g_off  [N_NODES + 1];
__device__ int   g_cursor[N_NODES];
__device__ int   g_esrc [N_EDGES];

// ---------------- prologue ----------------
__global__ void k_zero() {
    int i = blockIdx.x * blockDim.x + threadIdx.x;
    if (i < N_NODES) { g_cnt_s[i] = 0; g_cnt_r[i] = 0; }
}

__global__ void k_count(const int* __restrict__ snd, const int* __restrict__ rcv) {
    int e = blockIdx.x * blockDim.x + threadIdx.x;
    if (e < N_EDGES) {
        atomicAdd(&g_cnt_s[snd[e]], 1);
        atomicAdd(&g_cnt_r[rcv[e]], 1);
    }
}

// single-block scan over receiver counts; also emits inv_sqrt of sender degree
__global__ __launch_bounds__(1024) void k_scan_all() {
    __shared__ int warp_sums[32];
    const int t = threadIdx.x;
    const int lane = t & 31;
    const int wid = t >> 5;
    int base = 0;

    const int NT = (N_NODES + 1023) / 1024;
    for (int j = 0; j < NT; j++) {
        int i = j * 1024 + t;
        int v = (i < N_NODES) ? g_cnt_r[i] : 0;
        int x = v;
        #pragma unroll
        for (int d = 1; d < 32; d <<= 1) {
            int y = __shfl_up_sync(0xFFFFFFFFu, x, d);
            if (lane >= d) x += y;
        }
        if (lane == 31) warp_sums[wid] = x;
        __syncthreads();
        if (t < 32) {
            int y = warp_sums[t];
            #pragma unroll
            for (int d = 1; d < 32; d <<= 1) {
                int z = __shfl_up_sync(0xFFFFFFFFu, y, d);
                if (t >= d) y += z;
            }
            warp_sums[t] = y;
        }
        __syncthreads();
        int incl = x + (wid ? warp_sums[wid - 1] : 0);
        int total = warp_sums[31];
        int excl = base + incl - v;
        if (i < N_NODES) {
            g_off[i] = excl;
            g_cursor[i] = excl;
            g_inv_s[i] = rsqrtf(fmaxf((float)g_cnt_s[i], 1.0f));
        }
        base += total;
        __syncthreads();
    }
    if (t == 0) g_off[N_NODES] = N_EDGES;
}

__global__ void k_fill(const int* __restrict__ snd, const int* __restrict__ rcv) {
    int e = blockIdx.x * blockDim.x + threadIdx.x;
    if (e < N_EDGES) {
        int r = rcv[e];
        int pos = atomicAdd(&g_cursor[r], 1);
        g_esrc[pos] = snd[e];
    }
}

// ---------------- embed ----------------
__global__ void k_embed(const float* __restrict__ nodes,
                        const float* __restrict__ Wemb,
                        const float* __restrict__ bemb) {
    int idx = blockIdx.x * blockDim.x + threadIdx.x;
    if (idx >= N_NODES * LATENT) return;
    int n = idx >> 7;
    int c = idx & 127;
    float acc = bemb[c];
    #pragma unroll
    for (int k = 0; k < IN_FEAT; k++)
        acc = fmaf(nodes[n * IN_FEAT + k], Wemb[k * LATENT + c], acc);
    g_h[idx] = acc;
}

// ---------------- fused dual GEMM (proven R4 version, 81.6us) ----------------
// x2 = relu( relu(h @ W0 + b0) @ W1 + b1 )   for a 64-row stripe.
__global__ __launch_bounds__(256) void k_gemm2(const float* __restrict__ W0,
                                               const float* __restrict__ b0,
                                               const float* __restrict__ W1,
                                               const float* __restrict__ b1) {
    const float* __restrict__ A = g_h;
    float* __restrict__ C = g_x2;

    __shared__ float Ast[16][65];     // stage-1 A chunk, transposed [k][row]
    __shared__ float Ws[16][128];     // weight chunk [k][col]
    __shared__ float X1[64 * 128];    // intermediate tile [row][col]

    const int tid = threadIdx.x;
    const int tx = tid & 31;          // col group (cols tx*4 .. +3)
    const int ty = tid >> 5;          // row group (rows ty*8 .. +7)
    const int rowBase = blockIdx.x * 64;

    const int ar = tid >> 2;          // 0..63
    const int kq = (tid & 3) * 4;     // 0,4,8,12
    const int wr = tid >> 5;          // 0..7
    const int wc = (tid & 31) * 4;    // 0..124

    float acc[8][4];
    #pragma unroll
    for (int i = 0; i < 8; i++)
        #pragma unroll
        for (int j = 0; j < 4; j++) acc[i][j] = 0.f;

    // ---------- stage 1: X1 = relu(A @ W0 + b0) ----------
    const bool arOK = (rowBase + ar) < N_NODES;
    for (int k0 = 0; k0 < 128; k0 += 16) {
        {
            float4 v = arOK ? *(const float4*)&A[(size_t)(rowBase + ar) * 128 + k0 + kq]
                            : make_float4(0.f, 0.f, 0.f, 0.f);
            Ast[kq + 0][ar] = v.x;
            Ast[kq + 1][ar] = v.y;
            Ast[kq + 2][ar] = v.z;
            Ast[kq + 3][ar] = v.w;
            *(float4*)&Ws[wr][wc]     = *(const float4*)&W0[(k0 + wr) * 128 + wc];
            *(float4*)&Ws[wr + 8][wc] = *(const float4*)&W0[(k0 + wr + 8) * 128 + wc];
        }
        __syncthreads();
        #pragma unroll
        for (int k = 0; k < 16; k++) {
            float4 wv = *(const float4*)&Ws[k][tx * 4];
            float a[8];
            #pragma unroll
            for (int i = 0; i < 8; i++) a[i] = Ast[k][ty * 8 + i];
            #pragma unroll
            for (int i = 0; i < 8; i++) {
                acc[i][0] = fmaf(a[i], wv.x, acc[i][0]);
                acc[i][1] = fmaf(a[i], wv.y, acc[i][1]);
                acc[i][2] = fmaf(a[i], wv.z, acc[i][2]);
                acc[i][3] = fmaf(a[i], wv.w, acc[i][3]);
            }
        }
        __syncthreads();
    }
    {
        float4 bv = *(const float4*)&b0[tx * 4];
        #pragma unroll
        for (int i = 0; i < 8; i++) {
            float4 o;
            o.x = fmaxf(acc[i][0] + bv.x, 0.f);
            o.y = fmaxf(acc[i][1] + bv.y, 0.f);
            o.z = fmaxf(acc[i][2] + bv.z, 0.f);
            o.w = fmaxf(acc[i][3] + bv.w, 0.f);
            *(float4*)&X1[(ty * 8 + i) * 128 + tx * 4] = o;
        }
    }
    __syncthreads();

    // ---------- stage 2: x2 = relu(X1 @ W1 + b1) ----------
    #pragma unroll
    for (int i = 0; i < 8; i++)
        #pragma unroll
        for (int j = 0; j < 4; j++) acc[i][j] = 0.f;

    for (int k0 = 0; k0 < 128; k0 += 16) {
        *(float4*)&Ws[wr][wc]     = *(const float4*)&W1[(k0 + wr) * 128 + wc];
        *(float4*)&Ws[wr + 8][wc] = *(const float4*)&W1[(k0 + wr + 8) * 128 + wc];
        __syncthreads();
        #pragma unroll
        for (int k = 0; k < 16; k++) {
            float4 wv = *(const float4*)&Ws[k][tx * 4];
            float a[8];
            #pragma unroll
            for (int i = 0; i < 8; i++) a[i] = X1[(ty * 8 + i) * 128 + k0 + k];
            #pragma unroll
            for (int i = 0; i < 8; i++) {
                acc[i][0] = fmaf(a[i], wv.x, acc[i][0]);
                acc[i][1] = fmaf(a[i], wv.y, acc[i][1]);
                acc[i][2] = fmaf(a[i], wv.z, acc[i][2]);
                acc[i][3] = fmaf(a[i], wv.w, acc[i][3]);
            }
        }
        __syncthreads();
    }
    {
        float4 bv = *(const float4*)&b1[tx * 4];
        #pragma unroll
        for (int i = 0; i < 8; i++) {
            int row = rowBase + ty * 8 + i;
            if (row >= N_NODES) break;
            float4 o;
            o.x = fmaxf(acc[i][0] + bv.x, 0.f);
            o.y = fmaxf(acc[i][1] + bv.y, 0.f);
            o.z = fmaxf(acc[i][2] + bv.z, 0.f);
            o.w = fmaxf(acc[i][3] + bv.w, 0.f);
            *(float4*)&C[(size_t)row * 128 + tx * 4] = o;
        }
    }
}

// ---------------- fused aggregate + skip + LayerNorm (+ optional decode) ----
// one warp per node; unroll-4 gather for MLP; last step decodes directly to out.
__global__ __launch_bounds__(256) void k_agg_ln(const float* __restrict__ ln_scale,
                                                const float* __restrict__ ln_bias,
                                                const float* __restrict__ Wdec,
                                                const float* __restrict__ bdec,
                                                float* __restrict__ out,
                                                int doDecode) {
    int node = blockIdx.x * 8 + (threadIdx.x >> 5);
    if (node >= N_NODES) return;
    int lane = threadIdx.x & 31;

    int b0 = g_off[node], b1 = g_off[node + 1];
    float4 a0 = make_float4(0.f, 0.f, 0.f, 0.f);
    float4 a1 = make_float4(0.f, 0.f, 0.f, 0.f);
    float4 a2 = make_float4(0.f, 0.f, 0.f, 0.f);
    float4 a3 = make_float4(0.f, 0.f, 0.f, 0.f);
    int j = b0;
    for (; j + 3 < b1; j += 4) {
        int s0 = g_esrc[j],     s1 = g_esrc[j + 1];
        int s2 = g_esrc[j + 2], s3 = g_esrc[j + 3];
        float is0 = g_inv_s[s0], is1 = g_inv_s[s1];
        float is2 = g_inv_s[s2], is3 = g_inv_s[s3];
        float4 v0 = *(const float4*)&g_x2[(size_t)s0 * 128 + lane * 4];
        float4 v1 = *(const float4*)&g_x2[(size_t)s1 * 128 + lane * 4];
        float4 v2 = *(const float4*)&g_x2[(size_t)s2 * 128 + lane * 4];
        float4 v3 = *(const float4*)&g_x2[(size_t)s3 * 128 + lane * 4];
        a0.x = fmaf(v0.x, is0, a0.x); a0.y = fmaf(v0.y, is0, a0.y);
        a0.z = fmaf(v0.z, is0, a0.z); a0.w = fmaf(v0.w, is0, a0.w);
        a1.x = fmaf(v1.x, is1, a1.x); a1.y = fmaf(v1.y, is1, a1.y);
        a1.z = fmaf(v1.z, is1, a1.z); a1.w = fmaf(v1.w, is1, a1.w);
        a2.x = fmaf(v2.x, is2, a2.x); a2.y = fmaf(v2.y, is2, a2.y);
        a2.z = fmaf(v2.z, is2, a2.z); a2.w = fmaf(v2.w, is2, a2.w);
        a3.x = fmaf(v3.x, is3, a3.x); a3.y = fmaf(v3.y, is3, a3.y);
        a3.z = fmaf(v3.z, is3, a3.z); a3.w = fmaf(v3.w, is3, a3.w);
    }
    for (; j < b1; j++) {
        int s0 = g_esrc[j];
        float is0 = g_inv_s[s0];
        float4 v0 = *(const float4*)&g_x2[(size_t)s0 * 128 + lane * 4];
        a0.x = fmaf(v0.x, is0, a0.x); a0.y = fmaf(v0.y, is0, a0.y);
        a0.z = fmaf(v0.z, is0, a0.z); a0.w = fmaf(v0.w, is0, a0.w);
    }
    float4 acc;
    acc.x = (a0.x + a1.x) + (a2.x + a3.x);
    acc.y = (a0.y + a1.y) + (a2.y + a3.y);
    acc.z = (a0.z + a1.z) + (a2.z + a3.z);
    acc.w = (a0.w + a1.w) + (a2.w + a3.w);

    float invr = rsqrtf(fmaxf((float)(b1 - b0), 1.0f));
    float4 hv = *(const float4*)&g_h[(size_t)node * 128 + lane * 4];
    float4 u;
    u.x = fmaf(acc.x, invr, hv.x);
    u.y = fmaf(acc.y, invr, hv.y);
    u.z = fmaf(acc.z, invr, hv.z);
    u.w = fmaf(acc.w, invr, hv.w);

    float sum = u.x + u.y + u.z + u.w;
    float sq  = u.x * u.x + u.y * u.y + u.z * u.z + u.w * u.w;
    #pragma unroll
    for (int d = 16; d > 0; d >>= 1) {
        sum += __shfl_xor_sync(0xFFFFFFFFu, sum, d);
        sq  += __shfl_xor_sync(0xFFFFFFFFu, sq, d);
    }
    float mean = sum * (1.0f / 128.0f);
    float var = sq * (1.0f / 128.0f) - mean * mean;
    float rstd = rsqrtf(var + 1e-6f);

    float4 sc = *(const float4*)&ln_scale[lane * 4];
    float4 bi = *(const float4*)&ln_bias[lane * 4];
    float4 o;
    o.x = (u.x - mean) * rstd * sc.x + bi.x;
    o.y = (u.y - mean) * rstd * sc.y + bi.y;
    o.z = (u.z - mean) * rstd * sc.z + bi.z;
    o.w = (u.w - mean) * rstd * sc.w + bi.w;

    if (!doDecode) {
        *(float4*)&g_h[(size_t)node * 128 + lane * 4] = o;
    } else {
        // final step: h is only needed by the decoder -> decode in-register
        #pragma unroll
        for (int jj = 0; jj < IN_FEAT; jj++) {
            float p = o.x * __ldg(&Wdec[(lane * 4 + 0) * IN_FEAT + jj])
                    + o.y * __ldg(&Wdec[(lane * 4 + 1) * IN_FEAT + jj])
                    + o.z * __ldg(&Wdec[(lane * 4 + 2) * IN_FEAT + jj])
                    + o.w * __ldg(&Wdec[(lane * 4 + 3) * IN_FEAT + jj]);
            #pragma unroll
            for (int d = 16; d > 0; d >>= 1)
                p += __shfl_xor_sync(0xFFFFFFFFu, p, d);
            if (lane == jj) out[node * IN_FEAT + jj] = p + __ldg(&bdec[jj]);
        }
    }
}

extern "C" void kernel_launch(void* const* d_in, const int* in_sizes, int n_in,
                              void* d_out, int out_size) {
    const float* nodes    = (const float*)d_in[0];
    const int*   senders  = (const int*)  d_in[1];
    const int*   receivers= (const int*)  d_in[2];
    const float* W_embed  = (const float*)d_in[3];
    const float* b_embed  = (const float*)d_in[4];
    const float* mlp_W    = (const float*)d_in[5];
    const float* mlp_b    = (const float*)d_in[6];
    const float* ln_scale = (const float*)d_in[7];
    const float* ln_bias  = (const float*)d_in[8];
    const float* W_dec    = (const float*)d_in[9];
    const float* b_dec    = (const float*)d_in[10];
    float* out = (float*)d_out;

    const int GEMM_GRID = (N_NODES + 63) / 64;   // 782

    // launch index 3 = k_gemm2 (step 0) -> what ncu captures
    k_zero <<<(N_NODES + 255) / 256, 256>>>();                                   // 0
    k_count<<<(N_EDGES + 255) / 256, 256>>>(senders, receivers);                 // 1
    k_embed<<<(N_NODES * LATENT + 255) / 256, 256>>>(nodes, W_embed, b_embed);   // 2
    k_gemm2<<<GEMM_GRID, 256>>>(mlp_W, mlp_b,                                    // 3
                                mlp_W + (size_t)LATENT * LATENT, mlp_b + LATENT);
    k_scan_all<<<1, 1024>>>();                                                   // 4
    k_fill <<<(N_EDGES + 255) / 256, 256>>>(senders, receivers);                 // 5

    for (int step = 0; step < STEPS; step++) {
        if (step > 0) {
            const float* W0 = mlp_W + (size_t)(step * 2 + 0) * LATENT * LATENT;
            const float* W1 = mlp_W + (size_t)(step * 2 + 1) * LATENT * LATENT;
            const float* b0 = mlp_b + (size_t)(step * 2 + 0) * LATENT;
            const float* b1 = mlp_b + (size_t)(step * 2 + 1) * LATENT;
            k_gemm2<<<GEMM_GRID, 256>>>(W0, b0, W1, b1);
        }
        k_agg_ln<<<(N_NODES + 7) / 8, 256>>>(ln_scale + step * LATENT,
                                             ln_bias + step * LATENT,
                                             W_dec, b_dec, out,
                                             step == STEPS - 1 ? 1 : 0);
    }
}

// round 11
// speedup vs baseline: 2.0420x; 2.0420x over previous
#include <cuda_runtime.h>
#include <cuda_bf16.h>
#include <cstdint>

#define N_NODES 50000
#define N_PAD   50048            // 782 * 64
#define N_EDGES 600000
#define LATENT 128
#define IN_FEAT 7
#define STEPS 3

// -------- scratch (static device globals; zero-initialized) --------
__device__ float g_h [N_PAD * LATENT];
__device__ float g_x2[N_PAD * LATENT];
__device__ float g_inv_s[N_NODES];
__device__ int   g_cnt_s[N_NODES];
__device__ int   g_cnt_r[N_NODES];
__device__ int   g_off  [N_NODES + 1];
__device__ int   g_cursor[N_NODES];
__device__ int   g_esrc [N_EDGES];
// pre-split weights, [mat][hi 128x136][lo 128x136] bf16, row = n, col = k
__device__ __align__(16) __nv_bfloat16 g_Wbf[6 * 2 * 128 * 136];

// ---------------- helpers ----------------
__device__ __forceinline__ void cp16(uint32_t dst, const void* src) {
    asm volatile("cp.async.ca.shared.global [%0], [%1], 16;" :: "r"(dst), "l"(src));
}
__device__ __forceinline__ void cp_commit() {
    asm volatile("cp.async.commit_group;");
}
template <int N>
__device__ __forceinline__ void cp_wait() {
    asm volatile("cp.async.wait_group %0;" :: "n"(N));
}
// pack two fp32 into bf16x2 (lo half = first arg)
__device__ __forceinline__ uint32_t pack_bf(float lo, float hi) {
    uint32_t r;
    asm("cvt.rn.bf16x2.f32 %0, %1, %2;" : "=r"(r) : "f"(hi), "f"(lo));
    return r;
}
// split (c0,c1) into hi bf16x2 + residual-lo bf16x2
__device__ __forceinline__ void splitpair(float c0, float c1,
                                          uint32_t& h, uint32_t& l) {
    h = pack_bf(c0, c1);
    float h0 = __uint_as_float(h << 16);
    float h1 = __uint_as_float(h & 0xffff0000u);
    l = pack_bf(c0 - h0, c1 - h1);
}
__device__ __forceinline__ void ldm4(uint32_t* r, uint32_t addr) {
    asm volatile("ldmatrix.sync.aligned.m8n8.x4.shared.b16 {%0,%1,%2,%3}, [%4];"
                 : "=r"(r[0]), "=r"(r[1]), "=r"(r[2]), "=r"(r[3]) : "r"(addr));
}
__device__ __forceinline__ void mma16816(float* d, const uint32_t* a,
                                         uint32_t b0, uint32_t b1) {
    asm volatile(
        "mma.sync.aligned.m16n8k16.row.col.f32.bf16.bf16.f32 "
        "{%0,%1,%2,%3}, {%4,%5,%6,%7}, {%8,%9}, {%0,%1,%2,%3};"
        : "+f"(d[0]), "+f"(d[1]), "+f"(d[2]), "+f"(d[3])
        : "r"(a[0]), "r"(a[1]), "r"(a[2]), "r"(a[3]), "r"(b0), "r"(b1));
}

// ---------------- prologue ----------------
__global__ void k_zero() {
    int i = blockIdx.x * blockDim.x + threadIdx.x;
    if (i < N_NODES) { g_cnt_s[i] = 0; g_cnt_r[i] = 0; }
}

__global__ void k_count(const int* __restrict__ snd, const int* __restrict__ rcv) {
    int e = blockIdx.x * blockDim.x + threadIdx.x;
    if (e < N_EDGES) {
        atomicAdd(&g_cnt_s[snd[e]], 1);
        atomicAdd(&g_cnt_r[rcv[e]], 1);
    }
}

__global__ __launch_bounds__(1024) void k_scan_all() {
    __shared__ int warp_sums[32];
    const int t = threadIdx.x;
    const int lane = t & 31;
    const int wid = t >> 5;
    int base = 0;

    const int NT = (N_NODES + 1023) / 1024;
    for (int j = 0; j < NT; j++) {
        int i = j * 1024 + t;
        int v = (i < N_NODES) ? g_cnt_r[i] : 0;
        int x = v;
        #pragma unroll
        for (int d = 1; d < 32; d <<= 1) {
            int y = __shfl_up_sync(0xFFFFFFFFu, x, d);
            if (lane >= d) x += y;
        }
        if (lane == 31) warp_sums[wid] = x;
        __syncthreads();
        if (t < 32) {
            int y = warp_sums[t];
            #pragma unroll
            for (int d = 1; d < 32; d <<= 1) {
                int z = __shfl_up_sync(0xFFFFFFFFu, y, d);
                if (t >= d) y += z;
            }
            warp_sums[t] = y;
        }
        __syncthreads();
        int incl = x + (wid ? warp_sums[wid - 1] : 0);
        int total = warp_sums[31];
        int excl = base + incl - v;
        if (i < N_NODES) {
            g_off[i] = excl;
            g_cursor[i] = excl;
            g_inv_s[i] = rsqrtf(fmaxf((float)g_cnt_s[i], 1.0f));
        }
        base += total;
        __syncthreads();
    }
    if (t == 0) g_off[N_NODES] = N_EDGES;
}

__global__ void k_fill(const int* __restrict__ snd, const int* __restrict__ rcv) {
    int e = blockIdx.x * blockDim.x + threadIdx.x;
    if (e < N_EDGES) {
        int r = rcv[e];
        int pos = atomicAdd(&g_cursor[r], 1);
        g_esrc[pos] = snd[e];
    }
}

// ---------------- weight pre-split: W[k][n] fp32 -> [n][k] bf16 hi/lo ------
__global__ void k_wsplit6(const float* __restrict__ mlpW) {
    int i = blockIdx.x * blockDim.x + threadIdx.x;
    if (i >= 6 * 16384) return;
    int mat = i >> 14;
    int rem = i & 16383;
    int n = rem >> 7;
    int k = rem & 127;
    float wv = mlpW[(size_t)mat * 16384 + k * 128 + n];
    __nv_bfloat16 h = __float2bfloat16(wv);
    float fh = __bfloat162float(h);
    __nv_bfloat16 l = __float2bfloat16(wv - fh);
    size_t base = (size_t)mat * 34816 + n * 136 + k;
    g_Wbf[base] = h;
    g_Wbf[base + 17408] = l;
}

// ---------------- embed ----------------
__global__ void k_embed(const float* __restrict__ nodes,
                        const float* __restrict__ Wemb,
                        const float* __restrict__ bemb) {
    int idx = blockIdx.x * blockDim.x + threadIdx.x;
    if (idx >= N_NODES * LATENT) return;
    int n = idx >> 7;
    int c = idx & 127;
    float acc = bemb[c];
    #pragma unroll
    for (int k = 0; k < IN_FEAT; k++)
        acc = fmaf(nodes[n * IN_FEAT + k], Wemb[k * LATENT + c], acc);
    g_h[idx] = acc;
}

// ---------------- fused dual GEMM on bf16 mma.sync (split hi/lo) ----------
// x2 = relu( relu(h @ W0 + b0) @ W1 + b1 ) for a 64-row stripe.
// A/X1 live in smem as bf16 hi/lo, pitch 136 halves (272B -> ldmatrix
// conflict-free). Weights pre-split in global, cp.async'd per stage.
#define PITCH 136
#define SM_AH 0
#define SM_AL 17408
#define SM_WH 34816
#define SM_WL 69632
#define SM_TOT 104448

__global__ __launch_bounds__(128) void k_gemm2bf(int step,
                                                 const float* __restrict__ b0,
                                                 const float* __restrict__ b1) {
    extern __shared__ __align__(16) unsigned char smem[];
    const uint32_t sb = (uint32_t)__cvta_generic_to_shared(smem);
    const int tid = threadIdx.x;
    const int lane = tid & 31;
    const int w = tid >> 5;
    const size_t rowBase = (size_t)blockIdx.x * 64;

    // start W0 (hi+lo, 69632B contiguous) streaming in
    const char* wsrc0 = (const char*)g_Wbf + (size_t)(2 * step) * 69632;
    #pragma unroll
    for (int i = 0; i < 34; i++)
        cp16(sb + SM_WH + (i * 128 + tid) * 16, wsrc0 + (i * 128 + tid) * 16);
    cp_commit();

    // convert A rows to bf16 hi/lo while W0 streams
    {
        int row = tid >> 1;
        int cbase = (tid & 1) * 64;
        const float* src = g_h + (rowBase + row) * 128 + cbase;
        uint32_t* dh = (uint32_t*)(smem + SM_AH) + (row * PITCH + cbase) / 2;
        uint32_t* dl = (uint32_t*)(smem + SM_AL) + (row * PITCH + cbase) / 2;
        #pragma unroll
        for (int i = 0; i < 16; i++) {
            float4 v = *(const float4*)(src + i * 4);
            uint32_t h0, l0, h1, l1;
            splitpair(v.x, v.y, h0, l0);
            splitpair(v.z, v.w, h1, l1);
            dh[i * 2]     = h0; dh[i * 2 + 1] = h1;
            dl[i * 2]     = l0; dl[i * 2 + 1] = l1;
        }
    }
    cp_wait<0>();
    __syncthreads();

    // per-lane ldmatrix addressing
    const int lr = (lane & 7) + ((lane >> 3) & 1) * 8;   // 0..15
    const int lc = (lane >> 4) * 8;                      // 0 or 8
    const uint32_t aH = sb + SM_AH + ((w * 16 + lr) * PITCH + lc) * 2;
    const uint32_t aL = sb + SM_AL + ((w * 16 + lr) * PITCH + lc) * 2;
    const uint32_t bOff = (lr * PITCH + lc) * 2;

    float d[16][4];
    #pragma unroll
    for (int t = 0; t < 16; t++)
        #pragma unroll
        for (int q = 0; q < 4; q++) d[t][q] = 0.f;

    // ---------- stage 1 mainloop ----------
    #pragma unroll
    for (int kc = 0; kc < 8; kc++) {
        uint32_t ah[4], al[4];
        ldm4(ah, aH + kc * 32);
        ldm4(al, aL + kc * 32);
        #pragma unroll
        for (int g8 = 0; g8 < 8; g8++) {
            uint32_t bh[4], bl[4];
            uint32_t go = (uint32_t)(g8 * 16 * PITCH * 2) + kc * 32 + bOff;
            ldm4(bh, sb + SM_WH + go);
            ldm4(bl, sb + SM_WL + go);
            mma16816(d[2 * g8],     ah, bh[0], bh[2]);
            mma16816(d[2 * g8],     al, bh[0], bh[2]);
            mma16816(d[2 * g8],     ah, bl[0], bl[2]);
            mma16816(d[2 * g8 + 1], ah, bh[1], bh[3]);
            mma16816(d[2 * g8 + 1], al, bh[1], bh[3]);
            mma16816(d[2 * g8 + 1], ah, bl[1], bl[3]);
        }
    }
    __syncthreads();   // all smem reads of stage 1 done

    // stream W1 in while doing the X1 epilogue
    const char* wsrc1 = (const char*)g_Wbf + (size_t)(2 * step + 1) * 69632;
    #pragma unroll
    for (int i = 0; i < 34; i++)
        cp16(sb + SM_WH + (i * 128 + tid) * 16, wsrc1 + (i * 128 + tid) * 16);
    cp_commit();

    // epilogue 1: X1 = relu(D + b0) -> split back into Ah/Al
    {
        const int g = lane >> 2, tig = lane & 3;
        const int rA = w * 16 + g, rB = rA + 8;
        uint32_t* hA = (uint32_t*)(smem + SM_AH);
        uint32_t* lA = (uint32_t*)(smem + SM_AL);
        #pragma unroll
        for (int t = 0; t < 16; t++) {
            int col = t * 8 + tig * 2;
            float bb0 = __ldg(&b0[col]), bb1 = __ldg(&b0[col + 1]);
            float u0 = fmaxf(d[t][0] + bb0, 0.f);
            float u1 = fmaxf(d[t][1] + bb1, 0.f);
            float u2 = fmaxf(d[t][2] + bb0, 0.f);
            float u3 = fmaxf(d[t][3] + bb1, 0.f);
            uint32_t h, l;
            splitpair(u0, u1, h, l);
            hA[(rA * PITCH + col) / 2] = h;
            lA[(rA * PITCH + col) / 2] = l;
            splitpair(u2, u3, h, l);
            hA[(rB * PITCH + col) / 2] = h;
            lA[(rB * PITCH + col) / 2] = l;
            d[t][0] = d[t][1] = d[t][2] = d[t][3] = 0.f;
        }
    }
    cp_wait<0>();
    __syncthreads();

    // ---------- stage 2 mainloop ----------
    #pragma unroll
    for (int kc = 0; kc < 8; kc++) {
        uint32_t ah[4], al[4];
        ldm4(ah, aH + kc * 32);
        ldm4(al, aL + kc * 32);
        #pragma unroll
        for (int g8 = 0; g8 < 8; g8++) {
            uint32_t bh[4], bl[4];
            uint32_t go = (uint32_t)(g8 * 16 * PITCH * 2) + kc * 32 + bOff;
            ldm4(bh, sb + SM_WH + go);
            ldm4(bl, sb + SM_WL + go);
            mma16816(d[2 * g8],     ah, bh[0], bh[2]);
            mma16816(d[2 * g8],     al, bh[0], bh[2]);
            mma16816(d[2 * g8],     ah, bl[0], bl[2]);
            mma16816(d[2 * g8 + 1], ah, bh[1], bh[3]);
            mma16816(d[2 * g8 + 1], al, bh[1], bh[3]);
            mma16816(d[2 * g8 + 1], ah, bl[1], bl[3]);
        }
    }

    // epilogue 2: x2 = relu(D + b1) -> global fp32
    {
        const int g = lane >> 2, tig = lane & 3;
        const int rA = w * 16 + g, rB = rA + 8;
        float* o0 = g_x2 + (rowBase + rA) * 128;
        float* o1 = g_x2 + (rowBase + rB) * 128;
        #pragma unroll
        for (int t = 0; t < 16; t++) {
            int col = t * 8 + tig * 2;
            float bb0 = __ldg(&b1[col]), bb1 = __ldg(&b1[col + 1]);
            float2 vA, vB;
            vA.x = fmaxf(d[t][0] + bb0, 0.f);
            vA.y = fmaxf(d[t][1] + bb1, 0.f);
            vB.x = fmaxf(d[t][2] + bb0, 0.f);
            vB.y = fmaxf(d[t][3] + bb1, 0.f);
            *(float2*)(o0 + col) = vA;
            *(float2*)(o1 + col) = vB;
        }
    }
}

// ---------------- fused aggregate + skip + LayerNorm (+ optional decode) ----
__global__ __launch_bounds__(256) void k_agg_ln(const float* __restrict__ ln_scale,
                                                const float* __restrict__ ln_bias,
                                                const float* __restrict__ Wdec,
                                                const float* __restrict__ bdec,
                                                float* __restrict__ out,
                                                int doDecode) {
    int node = blockIdx.x * 8 + (threadIdx.x >> 5);
    if (node >= N_NODES) return;
    int lane = threadIdx.x & 31;

    int b0 = g_off[node], b1 = g_off[node + 1];
    float4 a0 = make_float4(0.f, 0.f, 0.f, 0.f);
    float4 a1 = make_float4(0.f, 0.f, 0.f, 0.f);
    float4 a2 = make_float4(0.f, 0.f, 0.f, 0.f);
    float4 a3 = make_float4(0.f, 0.f, 0.f, 0.f);
    int j = b0;
    for (; j + 3 < b1; j += 4) {
        int s0 = g_esrc[j],     s1 = g_esrc[j + 1];
        int s2 = g_esrc[j + 2], s3 = g_esrc[j + 3];
        float is0 = g_inv_s[s0], is1 = g_inv_s[s1];
        float is2 = g_inv_s[s2], is3 = g_inv_s[s3];
        float4 v0 = *(const float4*)&g_x2[(size_t)s0 * 128 + lane * 4];
        float4 v1 = *(const float4*)&g_x2[(size_t)s1 * 128 + lane * 4];
        float4 v2 = *(const float4*)&g_x2[(size_t)s2 * 128 + lane * 4];
        float4 v3 = *(const float4*)&g_x2[(size_t)s3 * 128 + lane * 4];
        a0.x = fmaf(v0.x, is0, a0.x); a0.y = fmaf(v0.y, is0, a0.y);
        a0.z = fmaf(v0.z, is0, a0.z); a0.w = fmaf(v0.w, is0, a0.w);
        a1.x = fmaf(v1.x, is1, a1.x); a1.y = fmaf(v1.y, is1, a1.y);
        a1.z = fmaf(v1.z, is1, a1.z); a1.w = fmaf(v1.w, is1, a1.w);
        a2.x = fmaf(v2.x, is2, a2.x); a2.y = fmaf(v2.y, is2, a2.y);
        a2.z = fmaf(v2.z, is2, a2.z); a2.w = fmaf(v2.w, is2, a2.w);
        a3.x = fmaf(v3.x, is3, a3.x); a3.y = fmaf(v3.y, is3, a3.y);
        a3.z = fmaf(v3.z, is3, a3.z); a3.w = fmaf(v3.w, is3, a3.w);
    }
    for (; j < b1; j++) {
        int s0 = g_esrc[j];
        float is0 = g_inv_s[s0];
        float4 v0 = *(const float4*)&g_x2[(size_t)s0 * 128 + lane * 4];
        a0.x = fmaf(v0.x, is0, a0.x); a0.y = fmaf(v0.y, is0, a0.y);
        a0.z = fmaf(v0.z, is0, a0.z); a0.w = fmaf(v0.w, is0, a0.w);
    }
    float4 acc;
    acc.x = (a0.x + a1.x) + (a2.x + a3.x);
    acc.y = (a0.y + a1.y) + (a2.y + a3.y);
    acc.z = (a0.z + a1.z) + (a2.z + a3.z);
    acc.w = (a0.w + a1.w) + (a2.w + a3.w);

    float invr = rsqrtf(fmaxf((float)(b1 - b0), 1.0f));
    float4 hv = *(const float4*)&g_h[(size_t)node * 128 + lane * 4];
    float4 u;
    u.x = fmaf(acc.x, invr, hv.x);
    u.y = fmaf(acc.y, invr, hv.y);
    u.z = fmaf(acc.z, invr, hv.z);
    u.w = fmaf(acc.w, invr, hv.w);

    float sum = u.x + u.y + u.z + u.w;
    float sq  = u.x * u.x + u.y * u.y + u.z * u.z + u.w * u.w;
    #pragma unroll
    for (int d = 16; d > 0; d >>= 1) {
        sum += __shfl_xor_sync(0xFFFFFFFFu, sum, d);
        sq  += __shfl_xor_sync(0xFFFFFFFFu, sq, d);
    }
    float mean = sum * (1.0f / 128.0f);
    float var = sq * (1.0f / 128.0f) - mean * mean;
    float rstd = rsqrtf(var + 1e-6f);

    float4 sc = *(const float4*)&ln_scale[lane * 4];
    float4 bi = *(const float4*)&ln_bias[lane * 4];
    float4 o;
    o.x = (u.x - mean) * rstd * sc.x + bi.x;
    o.y = (u.y - mean) * rstd * sc.y + bi.y;
    o.z = (u.z - mean) * rstd * sc.z + bi.z;
    o.w = (u.w - mean) * rstd * sc.w + bi.w;

    if (!doDecode) {
        *(float4*)&g_h[(size_t)node * 128 + lane * 4] = o;
    } else {
        #pragma unroll
        for (int jj = 0; jj < IN_FEAT; jj++) {
            float p = o.x * __ldg(&Wdec[(lane * 4 + 0) * IN_FEAT + jj])
                    + o.y * __ldg(&Wdec[(lane * 4 + 1) * IN_FEAT + jj])
                    + o.z * __ldg(&Wdec[(lane * 4 + 2) * IN_FEAT + jj])
                    + o.w * __ldg(&Wdec[(lane * 4 + 3) * IN_FEAT + jj]);
            #pragma unroll
            for (int d = 16; d > 0; d >>= 1)
                p += __shfl_xor_sync(0xFFFFFFFFu, p, d);
            if (lane == jj) out[node * IN_FEAT + jj] = p + __ldg(&bdec[jj]);
        }
    }
}

extern "C" void kernel_launch(void* const* d_in, const int* in_sizes, int n_in,
                              void* d_out, int out_size) {
    const float* nodes    = (const float*)d_in[0];
    const int*   senders  = (const int*)  d_in[1];
    const int*   receivers= (const int*)  d_in[2];
    const float* W_embed  = (const float*)d_in[3];
    const float* b_embed  = (const float*)d_in[4];
    const float* mlp_W    = (const float*)d_in[5];
    const float* mlp_b    = (const float*)d_in[6];
    const float* ln_scale = (const float*)d_in[7];
    const float* ln_bias  = (const float*)d_in[8];
    const float* W_dec    = (const float*)d_in[9];
    const float* b_dec    = (const float*)d_in[10];
    float* out = (float*)d_out;

    cudaFuncSetAttribute(k_gemm2bf, cudaFuncAttributeMaxDynamicSharedMemorySize,
                         SM_TOT);

    const int GEMM_GRID = N_PAD / 64;    // 782

    // launch index 3 = k_gemm2bf (step 0) -> what ncu captures
    k_zero   <<<(N_NODES + 255) / 256, 256>>>();                                 // 0
    k_wsplit6<<<(6 * 16384 + 255) / 256, 256>>>(mlp_W);                          // 1
    k_embed  <<<(N_NODES * LATENT + 255) / 256, 256>>>(nodes, W_embed, b_embed); // 2
    k_gemm2bf<<<GEMM_GRID, 128, SM_TOT>>>(0, mlp_b, mlp_b + 128);                // 3
    k_count<<<(N_EDGES + 255) / 256, 256>>>(senders, receivers);                 // 4
    k_scan_all<<<1, 1024>>>();                                                   // 5
    k_fill <<<(N_EDGES + 255) / 256, 256>>>(senders, receivers);                 // 6

    for (int step = 0; step < STEPS; step++) {
        if (step > 0) {
            k_gemm2bf<<<GEMM_GRID, 128, SM_TOT>>>(step,
                                                  mlp_b + step * 256,
                                                  mlp_b + step * 256 + 128);
        }
        k_agg_ln<<<(N_NODES + 7) / 8, 256>>>(ln_scale + step * LATENT,
                                             ln_bias + step * LATENT,
                                             W_dec, b_dec, out,
                                             step == STEPS - 1 ? 1 : 0);
    }
}

// round 12
// speedup vs baseline: 2.0453x; 1.0016x over previous
#include <cuda_runtime.h>
#include <cuda_bf16.h>
#include <cstdint>

#define N_NODES 50000
#define N_PAD   50048            // 391 * 128
#define N_EDGES 600000
#define LATENT 128
#define IN_FEAT 7
#define STEPS 3

// -------- scratch (static device globals; zero-initialized) --------
__device__ float g_h [N_PAD * LATENT];
__device__ float g_x2[N_PAD * LATENT];
__device__ float g_inv_s[N_NODES];
__device__ int   g_cnt_s[N_NODES];
__device__ int   g_cnt_r[N_NODES];
__device__ int   g_off  [N_NODES + 1];
__device__ int   g_cursor[N_NODES];
__device__ int   g_esrc [N_EDGES];
// pre-split weights, [mat][hi 128x136][lo 128x136] bf16, row = n, col = k
__device__ __align__(16) __nv_bfloat16 g_Wbf[6 * 2 * 128 * 136];

// ---------------- helpers ----------------
__device__ __forceinline__ void cp16(uint32_t dst, const void* src) {
    asm volatile("cp.async.ca.shared.global [%0], [%1], 16;" :: "r"(dst), "l"(src));
}
__device__ __forceinline__ void cp_commit() {
    asm volatile("cp.async.commit_group;");
}
template <int N>
__device__ __forceinline__ void cp_wait() {
    asm volatile("cp.async.wait_group %0;" :: "n"(N));
}
__device__ __forceinline__ uint32_t pack_bf(float lo, float hi) {
    uint32_t r;
    asm("cvt.rn.bf16x2.f32 %0, %1, %2;" : "=r"(r) : "f"(hi), "f"(lo));
    return r;
}
__device__ __forceinline__ void splitpair(float c0, float c1,
                                          uint32_t& h, uint32_t& l) {
    h = pack_bf(c0, c1);
    float h0 = __uint_as_float(h << 16);
    float h1 = __uint_as_float(h & 0xffff0000u);
    l = pack_bf(c0 - h0, c1 - h1);
}
__device__ __forceinline__ void ldm4(uint32_t* r, uint32_t addr) {
    asm volatile("ldmatrix.sync.aligned.m8n8.x4.shared.b16 {%0,%1,%2,%3}, [%4];"
                 : "=r"(r[0]), "=r"(r[1]), "=r"(r[2]), "=r"(r[3]) : "r"(addr));
}
__device__ __forceinline__ void mma16816(float* d, const uint32_t* a,
                                         uint32_t b0, uint32_t b1) {
    asm volatile(
        "mma.sync.aligned.m16n8k16.row.col.f32.bf16.bf16.f32 "
        "{%0,%1,%2,%3}, {%4,%5,%6,%7}, {%8,%9}, {%0,%1,%2,%3};"
        : "+f"(d[0]), "+f"(d[1]), "+f"(d[2]), "+f"(d[3])
        : "r"(a[0]), "r"(a[1]), "r"(a[2]), "r"(a[3]), "r"(b0), "r"(b1));
}

// ---------------- prologue ----------------
__global__ void k_zero() {
    int i = blockIdx.x * blockDim.x + threadIdx.x;
    if (i < N_NODES) { g_cnt_s[i] = 0; g_cnt_r[i] = 0; }
}

__global__ void k_count(const int* __restrict__ snd, const int* __restrict__ rcv) {
    int e = blockIdx.x * blockDim.x + threadIdx.x;
    if (e < N_EDGES) {
        atomicAdd(&g_cnt_s[snd[e]], 1);
        atomicAdd(&g_cnt_r[rcv[e]], 1);
    }
}

__global__ __launch_bounds__(1024) void k_scan_all() {
    __shared__ int warp_sums[32];
    const int t = threadIdx.x;
    const int lane = t & 31;
    const int wid = t >> 5;
    int base = 0;

    const int NT = (N_NODES + 1023) / 1024;
    for (int j = 0; j < NT; j++) {
        int i = j * 1024 + t;
        int v = (i < N_NODES) ? g_cnt_r[i] : 0;
        int x = v;
        #pragma unroll
        for (int d = 1; d < 32; d <<= 1) {
            int y = __shfl_up_sync(0xFFFFFFFFu, x, d);
            if (lane >= d) x += y;
        }
        if (lane == 31) warp_sums[wid] = x;
        __syncthreads();
        if (t < 32) {
            int y = warp_sums[t];
            #pragma unroll
            for (int d = 1; d < 32; d <<= 1) {
                int z = __shfl_up_sync(0xFFFFFFFFu, y, d);
                if (t >= d) y += z;
            }
            warp_sums[t] = y;
        }
        __syncthreads();
        int incl = x + (wid ? warp_sums[wid - 1] : 0);
        int total = warp_sums[31];
        int excl = base + incl - v;
        if (i < N_NODES) {
            g_off[i] = excl;
            g_cursor[i] = excl;
            g_inv_s[i] = rsqrtf(fmaxf((float)g_cnt_s[i], 1.0f));
        }
        base += total;
        __syncthreads();
    }
    if (t == 0) g_off[N_NODES] = N_EDGES;
}

__global__ void k_fill(const int* __restrict__ snd, const int* __restrict__ rcv) {
    int e = blockIdx.x * blockDim.x + threadIdx.x;
    if (e < N_EDGES) {
        int r = rcv[e];
        int pos = atomicAdd(&g_cursor[r], 1);
        g_esrc[pos] = snd[e];
    }
}

// ---------------- weight pre-split: W[k][n] fp32 -> [n][k] bf16 hi/lo ------
__global__ void k_wsplit6(const float* __restrict__ mlpW) {
    int i = blockIdx.x * blockDim.x + threadIdx.x;
    if (i >= 6 * 16384) return;
    int mat = i >> 14;
    int rem = i & 16383;
    int n = rem >> 7;
    int k = rem & 127;
    float wv = mlpW[(size_t)mat * 16384 + k * 128 + n];
    __nv_bfloat16 h = __float2bfloat16(wv);
    float fh = __bfloat162float(h);
    __nv_bfloat16 l = __float2bfloat16(wv - fh);
    size_t base = (size_t)mat * 34816 + n * 136 + k;
    g_Wbf[base] = h;
    g_Wbf[base + 17408] = l;
}

// ---------------- embed ----------------
__global__ void k_embed(const float* __restrict__ nodes,
                        const float* __restrict__ Wemb,
                        const float* __restrict__ bemb) {
    int idx = blockIdx.x * blockDim.x + threadIdx.x;
    if (idx >= N_NODES * LATENT) return;
    int n = idx >> 7;
    int c = idx & 127;
    float acc = bemb[c];
    #pragma unroll
    for (int k = 0; k < IN_FEAT; k++)
        acc = fmaf(nodes[n * IN_FEAT + k], Wemb[k * LATENT + c], acc);
    g_h[idx] = acc;
}

// ---------------- fused dual GEMM on bf16 mma.sync (split hi/lo) ----------
// 128-row tile, 256 threads / 8 warps. Warp w: rows (w>>1)*32..+32,
// cols (w&1)*64..+64 -> B fragments amortized over 2 A tiles (96 LDSM : 384 MMA).
#define PITCH 136
#define SM_AH 0
#define SM_AL 34816
#define SM_WH 69632
#define SM_WL 104448
#define SM_TOT 139264

__global__ __launch_bounds__(256) void k_gemm2bf(int step,
                                                 const float* __restrict__ b0,
                                                 const float* __restrict__ b1) {
    extern __shared__ __align__(16) unsigned char smem[];
    const uint32_t sb = (uint32_t)__cvta_generic_to_shared(smem);
    const int tid = threadIdx.x;
    const int lane = tid & 31;
    const int w = tid >> 5;
    const size_t rowBase = (size_t)blockIdx.x * 128;

    // stream W0 (hi+lo, 69632B contiguous): 4352 uint4 / 256 thr = 17 iters
    const char* wsrc0 = (const char*)g_Wbf + (size_t)(2 * step) * 69632;
    #pragma unroll
    for (int i = 0; i < 17; i++)
        cp16(sb + SM_WH + (i * 256 + tid) * 16, wsrc0 + (i * 256 + tid) * 16);
    cp_commit();

    // convert A rows to bf16 hi/lo while W0 streams (thread = half row)
    {
        int row = tid >> 1;
        int cbase = (tid & 1) * 64;
        const float* src = g_h + (rowBase + row) * 128 + cbase;
        uint32_t* dh = (uint32_t*)(smem + SM_AH) + (row * PITCH + cbase) / 2;
        uint32_t* dl = (uint32_t*)(smem + SM_AL) + (row * PITCH + cbase) / 2;
        #pragma unroll
        for (int i = 0; i < 16; i++) {
            float4 v = *(const float4*)(src + i * 4);
            uint32_t h0, l0, h1, l1;
            splitpair(v.x, v.y, h0, l0);
            splitpair(v.z, v.w, h1, l1);
            dh[i * 2]     = h0; dh[i * 2 + 1] = h1;
            dl[i * 2]     = l0; dl[i * 2 + 1] = l1;
        }
    }
    cp_wait<0>();
    __syncthreads();

    // warp tile: rows r0..r0+32 (2 m16 tiles), cols c0..c0+64 (4 n16 groups)
    const int r0 = (w >> 1) * 32;
    const int c0 = (w & 1) * 64;
    const int lr = (lane & 7) + ((lane >> 3) & 1) * 8;   // 0..15
    const int lc = (lane >> 4) * 8;                      // 0 or 8
    const uint32_t aH0 = sb + SM_AH + ((r0 + lr) * PITCH + lc) * 2;
    const uint32_t aL0 = sb + SM_AL + ((r0 + lr) * PITCH + lc) * 2;
    const uint32_t tstride = 16 * PITCH * 2;
    const uint32_t bOff = (lr * PITCH + lc) * 2;

    float d[2][8][4];
    #pragma unroll
    for (int at = 0; at < 2; at++)
        #pragma unroll
        for (int nb = 0; nb < 8; nb++)
            #pragma unroll
            for (int q = 0; q < 4; q++) d[at][nb][q] = 0.f;

    // ---------- stage 1 mainloop ----------
    #pragma unroll
    for (int kc = 0; kc < 8; kc++) {
        uint32_t a0h[4], a0l[4], a1h[4], a1l[4];
        ldm4(a0h, aH0 + kc * 32);
        ldm4(a0l, aL0 + kc * 32);
        ldm4(a1h, aH0 + tstride + kc * 32);
        ldm4(a1l, aL0 + tstride + kc * 32);
        #pragma unroll
        for (int g16 = 0; g16 < 4; g16++) {
            uint32_t bh[4], bl[4];
            uint32_t go = (uint32_t)((c0 + g16 * 16) * PITCH * 2) + kc * 32 + bOff;
            ldm4(bh, sb + SM_WH + go);
            ldm4(bl, sb + SM_WL + go);
            mma16816(d[0][2 * g16],     a0h, bh[0], bh[2]);
            mma16816(d[0][2 * g16],     a0l, bh[0], bh[2]);
            mma16816(d[0][2 * g16],     a0h, bl[0], bl[2]);
            mma16816(d[0][2 * g16 + 1], a0h, bh[1], bh[3]);
            mma16816(d[0][2 * g16 + 1], a0l, bh[1], bh[3]);
            mma16816(d[0][2 * g16 + 1], a0h, bl[1], bl[3]);
            mma16816(d[1][2 * g16],     a1h, bh[0], bh[2]);
            mma16816(d[1][2 * g16],     a1l, bh[0], bh[2]);
            mma16816(d[1][2 * g16],     a1h, bl[0], bl[2]);
            mma16816(d[1][2 * g16 + 1], a1h, bh[1], bh[3]);
            mma16816(d[1][2 * g16 + 1], a1l, bh[1], bh[3]);
            mma16816(d[1][2 * g16 + 1], a1h, bl[1], bl[3]);
        }
    }
    __syncthreads();   // all smem reads of stage 1 done

    // stream W1 in while doing the X1 epilogue
    const char* wsrc1 = (const char*)g_Wbf + (size_t)(2 * step + 1) * 69632;
    #pragma unroll
    for (int i = 0; i < 17; i++)
        cp16(sb + SM_WH + (i * 256 + tid) * 16, wsrc1 + (i * 256 + tid) * 16);
    cp_commit();

    // epilogue 1: X1 = relu(D + b0) -> split back into Ah/Al
    {
        const int g = lane >> 2, tig = lane & 3;
        uint32_t* hA = (uint32_t*)(smem + SM_AH);
        uint32_t* lA = (uint32_t*)(smem + SM_AL);
        #pragma unroll
        for (int at = 0; at < 2; at++) {
            const int rA = r0 + at * 16 + g, rB = rA + 8;
            #pragma unroll
            for (int nb = 0; nb < 8; nb++) {
                int col = c0 + nb * 8 + tig * 2;
                float bb0 = __ldg(&b0[col]), bb1 = __ldg(&b0[col + 1]);
                float u0 = fmaxf(d[at][nb][0] + bb0, 0.f);
                float u1 = fmaxf(d[at][nb][1] + bb1, 0.f);
                float u2 = fmaxf(d[at][nb][2] + bb0, 0.f);
                float u3 = fmaxf(d[at][nb][3] + bb1, 0.f);
                uint32_t h, l;
                splitpair(u0, u1, h, l);
                hA[(rA * PITCH + col) / 2] = h;
                lA[(rA * PITCH + col) / 2] = l;
                splitpair(u2, u3, h, l);
                hA[(rB * PITCH + col) / 2] = h;
                lA[(rB * PITCH + col) / 2] = l;
                d[at][nb][0] = d[at][nb][1] = d[at][nb][2] = d[at][nb][3] = 0.f;
            }
        }
    }
    cp_wait<0>();
    __syncthreads();

    // ---------- stage 2 mainloop ----------
    #pragma unroll
    for (int kc = 0; kc < 8; kc++) {
        uint32_t a0h[4], a0l[4], a1h[4], a1l[4];
        ldm4(a0h, aH0 + kc * 32);
        ldm4(a0l, aL0 + kc * 32);
        ldm4(a1h, aH0 + tstride + kc * 32);
        ldm4(a1l, aL0 + tstride + kc * 32);
        #pragma unroll
        for (int g16 = 0; g16 < 4; g16++) {
            uint32_t bh[4], bl[4];
            uint32_t go = (uint32_t)((c0 + g16 * 16) * PITCH * 2) + kc * 32 + bOff;
            ldm4(bh, sb + SM_WH + go);
            ldm4(bl, sb + SM_WL + go);
            mma16816(d[0][2 * g16],     a0h, bh[0], bh[2]);
            mma16816(d[0][2 * g16],     a0l, bh[0], bh[2]);
            mma16816(d[0][2 * g16],     a0h, bl[0], bl[2]);
            mma16816(d[0][2 * g16 + 1], a0h, bh[1], bh[3]);
            mma16816(d[0][2 * g16 + 1], a0l, bh[1], bh[3]);
            mma16816(d[0][2 * g16 + 1], a0h, bl[1], bl[3]);
            mma16816(d[1][2 * g16],     a1h, bh[0], bh[2]);
            mma16816(d[1][2 * g16],     a1l, bh[0], bh[2]);
            mma16816(d[1][2 * g16],     a1h, bl[0], bl[2]);
            mma16816(d[1][2 * g16 + 1], a1h, bh[1], bh[3]);
            mma16816(d[1][2 * g16 + 1], a1l, bh[1], bh[3]);
            mma16816(d[1][2 * g16 + 1], a1h, bl[1], bl[3]);
        }
    }

    // epilogue 2: x2 = relu(D + b1) -> global fp32
    {
        const int g = lane >> 2, tig = lane & 3;
        #pragma unroll
        for (int at = 0; at < 2; at++) {
            const int rA = r0 + at * 16 + g, rB = rA + 8;
            float* o0 = g_x2 + (rowBase + rA) * 128;
            float* o1 = g_x2 + (rowBase + rB) * 128;
            #pragma unroll
            for (int nb = 0; nb < 8; nb++) {
                int col = c0 + nb * 8 + tig * 2;
                float bb0 = __ldg(&b1[col]), bb1 = __ldg(&b1[col + 1]);
                float2 vA, vB;
                vA.x = fmaxf(d[at][nb][0] + bb0, 0.f);
                vA.y = fmaxf(d[at][nb][1] + bb1, 0.f);
                vB.x = fmaxf(d[at][nb][2] + bb0, 0.f);
                vB.y = fmaxf(d[at][nb][3] + bb1, 0.f);
                *(float2*)(o0 + col) = vA;
                *(float2*)(o1 + col) = vB;
            }
        }
    }
}

// ---------------- fused aggregate + skip + LayerNorm (+ optional decode) ----
__global__ __launch_bounds__(256) void k_agg_ln(const float* __restrict__ ln_scale,
                                                const float* __restrict__ ln_bias,
                                                const float* __restrict__ Wdec,
                                                const float* __restrict__ bdec,
                                                float* __restrict__ out,
                                                int doDecode) {
    int node = blockIdx.x * 8 + (threadIdx.x >> 5);
    if (node >= N_NODES) return;
    int lane = threadIdx.x & 31;

    int b0 = g_off[node], b1 = g_off[node + 1];
    float4 a0 = make_float4(0.f, 0.f, 0.f, 0.f);
    float4 a1 = make_float4(0.f, 0.f, 0.f, 0.f);
    float4 a2 = make_float4(0.f, 0.f, 0.f, 0.f);
    float4 a3 = make_float4(0.f, 0.f, 0.f, 0.f);
    int j = b0;
    for (; j + 3 < b1; j += 4) {
        int s0 = g_esrc[j],     s1 = g_esrc[j + 1];
        int s2 = g_esrc[j + 2], s3 = g_esrc[j + 3];
        float is0 = g_inv_s[s0], is1 = g_inv_s[s1];
        float is2 = g_inv_s[s2], is3 = g_inv_s[s3];
        float4 v0 = *(const float4*)&g_x2[(size_t)s0 * 128 + lane * 4];
        float4 v1 = *(const float4*)&g_x2[(size_t)s1 * 128 + lane * 4];
        float4 v2 = *(const float4*)&g_x2[(size_t)s2 * 128 + lane * 4];
        float4 v3 = *(const float4*)&g_x2[(size_t)s3 * 128 + lane * 4];
        a0.x = fmaf(v0.x, is0, a0.x); a0.y = fmaf(v0.y, is0, a0.y);
        a0.z = fmaf(v0.z, is0, a0.z); a0.w = fmaf(v0.w, is0, a0.w);
        a1.x = fmaf(v1.x, is1, a1.x); a1.y = fmaf(v1.y, is1, a1.y);
        a1.z = fmaf(v1.z, is1, a1.z); a1.w = fmaf(v1.w, is1, a1.w);
        a2.x = fmaf(v2.x, is2, a2.x); a2.y = fmaf(v2.y, is2, a2.y);
        a2.z = fmaf(v2.z, is2, a2.z); a2.w = fmaf(v2.w, is2, a2.w);
        a3.x = fmaf(v3.x, is3, a3.x); a3.y = fmaf(v3.y, is3, a3.y);
        a3.z = fmaf(v3.z, is3, a3.z); a3.w = fmaf(v3.w, is3, a3.w);
    }
    for (; j < b1; j++) {
        int s0 = g_esrc[j];
        float is0 = g_inv_s[s0];
        float4 v0 = *(const float4*)&g_x2[(size_t)s0 * 128 + lane * 4];
        a0.x = fmaf(v0.x, is0, a0.x); a0.y = fmaf(v0.y, is0, a0.y);
        a0.z = fmaf(v0.z, is0, a0.z); a0.w = fmaf(v0.w, is0, a0.w);
    }
    float4 acc;
    acc.x = (a0.x + a1.x) + (a2.x + a3.x);
    acc.y = (a0.y + a1.y) + (a2.y + a3.y);
    acc.z = (a0.z + a1.z) + (a2.z + a3.z);
    acc.w = (a0.w + a1.w) + (a2.w + a3.w);

    float invr = rsqrtf(fmaxf((float)(b1 - b0), 1.0f));
    float4 hv = *(const float4*)&g_h[(size_t)node * 128 + lane * 4];
    float4 u;
    u.x = fmaf(acc.x, invr, hv.x);
    u.y = fmaf(acc.y, invr, hv.y);
    u.z = fmaf(acc.z, invr, hv.z);
    u.w = fmaf(acc.w, invr, hv.w);

    float sum = u.x + u.y + u.z + u.w;
    float sq  = u.x * u.x + u.y * u.y + u.z * u.z + u.w * u.w;
    #pragma unroll
    for (int d = 16; d > 0; d >>= 1) {
        sum += __shfl_xor_sync(0xFFFFFFFFu, sum, d);
        sq  += __shfl_xor_sync(0xFFFFFFFFu, sq, d);
    }
    float mean = sum * (1.0f / 128.0f);
    float var = sq * (1.0f / 128.0f) - mean * mean;
    float rstd = rsqrtf(var + 1e-6f);

    float4 sc = *(const float4*)&ln_scale[lane * 4];
    float4 bi = *(const float4*)&ln_bias[lane * 4];
    float4 o;
    o.x = (u.x - mean) * rstd * sc.x + bi.x;
    o.y = (u.y - mean) * rstd * sc.y + bi.y;
    o.z = (u.z - mean) * rstd * sc.z + bi.z;
    o.w = (u.w - mean) * rstd * sc.w + bi.w;

    if (!doDecode) {
        *(float4*)&g_h[(size_t)node * 128 + lane * 4] = o;
    } else {
        #pragma unroll
        for (int jj = 0; jj < IN_FEAT; jj++) {
            float p = o.x * __ldg(&Wdec[(lane * 4 + 0) * IN_FEAT + jj])
                    + o.y * __ldg(&Wdec[(lane * 4 + 1) * IN_FEAT + jj])
                    + o.z * __ldg(&Wdec[(lane * 4 + 2) * IN_FEAT + jj])
                    + o.w * __ldg(&Wdec[(lane * 4 + 3) * IN_FEAT + jj]);
            #pragma unroll
            for (int d = 16; d > 0; d >>= 1)
                p += __shfl_xor_sync(0xFFFFFFFFu, p, d);
            if (lane == jj) out[node * IN_FEAT + jj] = p + __ldg(&bdec[jj]);
        }
    }
}

extern "C" void kernel_launch(void* const* d_in, const int* in_sizes, int n_in,
                              void* d_out, int out_size) {
    const float* nodes    = (const float*)d_in[0];
    const int*   senders  = (const int*)  d_in[1];
    const int*   receivers= (const int*)  d_in[2];
    const float* W_embed  = (const float*)d_in[3];
    const float* b_embed  = (const float*)d_in[4];
    const float* mlp_W    = (const float*)d_in[5];
    const float* mlp_b    = (const float*)d_in[6];
    const float* ln_scale = (const float*)d_in[7];
    const float* ln_bias  = (const float*)d_in[8];
    const float* W_dec    = (const float*)d_in[9];
    const float* b_dec    = (const float*)d_in[10];
    float* out = (float*)d_out;

    cudaFuncSetAttribute(k_gemm2bf, cudaFuncAttributeMaxDynamicSharedMemorySize,
                         SM_TOT);

    const int GEMM_GRID = N_PAD / 128;   // 391

    // launch index 3 = k_gemm2bf (step 0) -> what ncu captures
    k_zero   <<<(N_NODES + 255) / 256, 256>>>();                                 // 0
    k_wsplit6<<<(6 * 16384 + 255) / 256, 256>>>(mlp_W);                          // 1
    k_embed  <<<(N_NODES * LATENT + 255) / 256, 256>>>(nodes, W_embed, b_embed); // 2
    k_gemm2bf<<<GEMM_GRID, 256, SM_TOT>>>(0, mlp_b, mlp_b + 128);                // 3
    k_count<<<(N_EDGES + 255) / 256, 256>>>(senders, receivers);                 // 4
    k_scan_all<<<1, 1024>>>();                                                   // 5
    k_fill <<<(N_EDGES + 255) / 256, 256>>>(senders, receivers);                 // 6

    for (int step = 0; step < STEPS; step++) {
        if (step > 0) {
            k_gemm2bf<<<GEMM_GRID, 256, SM_TOT>>>(step,
                                                  mlp_b + step * 256,
                                                  mlp_b + step * 256 + 128);
        }
        k_agg_ln<<<(N_NODES + 7) / 8, 256>>>(ln_scale + step * LATENT,
                                             ln_bias + step * LATENT,
                                             W_dec, b_dec, out,
                                             step == STEPS - 1 ? 1 : 0);
    }
}

// round 13
// speedup vs baseline: 2.0878x; 1.0208x over previous
#include <cuda_runtime.h>
#include <cuda_bf16.h>
#include <cuda_fp16.h>
#include <cstdint>

#define N_NODES 50000
#define N_PAD   50048            // 391 * 128
#define N_EDGES 600000
#define LATENT 128
#define IN_FEAT 7
#define STEPS 3

// -------- scratch (static device globals; zero-initialized) --------
__device__ float  g_h [N_PAD * LATENT];
__device__ __half g_x2[N_PAD * LATENT];          // fp16 messages (scaled by inv_s)
__device__ float  g_inv_s[N_PAD];
__device__ int    g_cnt_s[N_NODES];
__device__ int    g_cnt_r[N_NODES];
__device__ int    g_off  [N_NODES + 1];
__device__ int    g_cursor[N_NODES];
__device__ int    g_esrc [N_EDGES];
// pre-split weights, [mat][hi 128x136][lo 128x136] bf16, row = n, col = k
__device__ __align__(16) __nv_bfloat16 g_Wbf[6 * 2 * 128 * 136];

// ---------------- helpers ----------------
__device__ __forceinline__ void cp16(uint32_t dst, const void* src) {
    asm volatile("cp.async.ca.shared.global [%0], [%1], 16;" :: "r"(dst), "l"(src));
}
__device__ __forceinline__ void cp_commit() {
    asm volatile("cp.async.commit_group;");
}
template <int N>
__device__ __forceinline__ void cp_wait() {
    asm volatile("cp.async.wait_group %0;" :: "n"(N));
}
__device__ __forceinline__ uint32_t pack_bf(float lo, float hi) {
    uint32_t r;
    asm("cvt.rn.bf16x2.f32 %0, %1, %2;" : "=r"(r) : "f"(hi), "f"(lo));
    return r;
}
__device__ __forceinline__ void splitpair(float c0, float c1,
                                          uint32_t& h, uint32_t& l) {
    h = pack_bf(c0, c1);
    float h0 = __uint_as_float(h << 16);
    float h1 = __uint_as_float(h & 0xffff0000u);
    l = pack_bf(c0 - h0, c1 - h1);
}
__device__ __forceinline__ void ldm4(uint32_t* r, uint32_t addr) {
    asm volatile("ldmatrix.sync.aligned.m8n8.x4.shared.b16 {%0,%1,%2,%3}, [%4];"
                 : "=r"(r[0]), "=r"(r[1]), "=r"(r[2]), "=r"(r[3]) : "r"(addr));
}
__device__ __forceinline__ void mma16816(float* d, const uint32_t* a,
                                         uint32_t b0, uint32_t b1) {
    asm volatile(
        "mma.sync.aligned.m16n8k16.row.col.f32.bf16.bf16.f32 "
        "{%0,%1,%2,%3}, {%4,%5,%6,%7}, {%8,%9}, {%0,%1,%2,%3};"
        : "+f"(d[0]), "+f"(d[1]), "+f"(d[2]), "+f"(d[3])
        : "r"(a[0]), "r"(a[1]), "r"(a[2]), "r"(a[3]), "r"(b0), "r"(b1));
}

// ---------------- prologue ----------------
__global__ void k_zero() {
    int i = blockIdx.x * blockDim.x + threadIdx.x;
    if (i < N_NODES) { g_cnt_s[i] = 0; g_cnt_r[i] = 0; }
}

__global__ void k_count(const int* __restrict__ snd, const int* __restrict__ rcv) {
    int e = blockIdx.x * blockDim.x + threadIdx.x;
    if (e < N_EDGES) {
        atomicAdd(&g_cnt_s[snd[e]], 1);
        atomicAdd(&g_cnt_r[rcv[e]], 1);
    }
}

__global__ __launch_bounds__(1024) void k_scan_all() {
    __shared__ int warp_sums[32];
    const int t = threadIdx.x;
    const int lane = t & 31;
    const int wid = t >> 5;
    int base = 0;

    const int NT = (N_NODES + 1023) / 1024;
    for (int j = 0; j < NT; j++) {
        int i = j * 1024 + t;
        int v = (i < N_NODES) ? g_cnt_r[i] : 0;
        int x = v;
        #pragma unroll
        for (int d = 1; d < 32; d <<= 1) {
            int y = __shfl_up_sync(0xFFFFFFFFu, x, d);
            if (lane >= d) x += y;
        }
        if (lane == 31) warp_sums[wid] = x;
        __syncthreads();
        if (t < 32) {
            int y = warp_sums[t];
            #pragma unroll
            for (int d = 1; d < 32; d <<= 1) {
                int z = __shfl_up_sync(0xFFFFFFFFu, y, d);
                if (t >= d) y += z;
            }
            warp_sums[t] = y;
        }
        __syncthreads();
        int incl = x + (wid ? warp_sums[wid - 1] : 0);
        int total = warp_sums[31];
        int excl = base + incl - v;
        if (i < N_NODES) {
            g_off[i] = excl;
            g_cursor[i] = excl;
            g_inv_s[i] = rsqrtf(fmaxf((float)g_cnt_s[i], 1.0f));
        }
        base += total;
        __syncthreads();
    }
    if (t == 0) g_off[N_NODES] = N_EDGES;
}

__global__ void k_fill(const int* __restrict__ snd, const int* __restrict__ rcv) {
    int e = blockIdx.x * blockDim.x + threadIdx.x;
    if (e < N_EDGES) {
        int r = rcv[e];
        int pos = atomicAdd(&g_cursor[r], 1);
        g_esrc[pos] = snd[e];
    }
}

// ---------------- weight pre-split: W[k][n] fp32 -> [n][k] bf16 hi/lo ------
__global__ void k_wsplit6(const float* __restrict__ mlpW) {
    int i = blockIdx.x * blockDim.x + threadIdx.x;
    if (i >= 6 * 16384) return;
    int mat = i >> 14;
    int rem = i & 16383;
    int n = rem >> 7;
    int k = rem & 127;
    float wv = mlpW[(size_t)mat * 16384 + k * 128 + n];
    __nv_bfloat16 h = __float2bfloat16(wv);
    float fh = __bfloat162float(h);
    __nv_bfloat16 l = __float2bfloat16(wv - fh);
    size_t base = (size_t)mat * 34816 + n * 136 + k;
    g_Wbf[base] = h;
    g_Wbf[base + 17408] = l;
}

// ---------------- embed ----------------
__global__ void k_embed(const float* __restrict__ nodes,
                        const float* __restrict__ Wemb,
                        const float* __restrict__ bemb) {
    int idx = blockIdx.x * blockDim.x + threadIdx.x;
    if (idx >= N_NODES * LATENT) return;
    int n = idx >> 7;
    int c = idx & 127;
    float acc = bemb[c];
    #pragma unroll
    for (int k = 0; k < IN_FEAT; k++)
        acc = fmaf(nodes[n * IN_FEAT + k], Wemb[k * LATENT + c], acc);
    g_h[idx] = acc;
}

// ---------------- fused dual GEMM on bf16 mma.sync (split hi/lo) ----------
// x2 = relu( relu(h@W0+b0) @ W1 + b1 ) * inv_s[row], stored as fp16.
#define PITCH 136
#define SM_AH 0
#define SM_AL 34816
#define SM_WH 69632
#define SM_WL 104448
#define SM_TOT 139264

__global__ __launch_bounds__(256) void k_gemm2bf(int step,
                                                 const float* __restrict__ b0,
                                                 const float* __restrict__ b1) {
    extern __shared__ __align__(16) unsigned char smem[];
    const uint32_t sb = (uint32_t)__cvta_generic_to_shared(smem);
    const int tid = threadIdx.x;
    const int lane = tid & 31;
    const int w = tid >> 5;
    const size_t rowBase = (size_t)blockIdx.x * 128;

    const char* wsrc0 = (const char*)g_Wbf + (size_t)(2 * step) * 69632;
    #pragma unroll
    for (int i = 0; i < 17; i++)
        cp16(sb + SM_WH + (i * 256 + tid) * 16, wsrc0 + (i * 256 + tid) * 16);
    cp_commit();

    // convert A rows to bf16 hi/lo while W0 streams (thread = half row)
    {
        int row = tid >> 1;
        int cbase = (tid & 1) * 64;
        const float* src = g_h + (rowBase + row) * 128 + cbase;
        uint32_t* dh = (uint32_t*)(smem + SM_AH) + (row * PITCH + cbase) / 2;
        uint32_t* dl = (uint32_t*)(smem + SM_AL) + (row * PITCH + cbase) / 2;
        #pragma unroll
        for (int i = 0; i < 16; i++) {
            float4 v = *(const float4*)(src + i * 4);
            uint32_t h0, l0, h1, l1;
            splitpair(v.x, v.y, h0, l0);
            splitpair(v.z, v.w, h1, l1);
            dh[i * 2]     = h0; dh[i * 2 + 1] = h1;
            dl[i * 2]     = l0; dl[i * 2 + 1] = l1;
        }
    }
    cp_wait<0>();
    __syncthreads();

    const int r0 = (w >> 1) * 32;
    const int c0 = (w & 1) * 64;
    const int lr = (lane & 7) + ((lane >> 3) & 1) * 8;
    const int lc = (lane >> 4) * 8;
    const uint32_t aH0 = sb + SM_AH + ((r0 + lr) * PITCH + lc) * 2;
    const uint32_t aL0 = sb + SM_AL + ((r0 + lr) * PITCH + lc) * 2;
    const uint32_t tstride = 16 * PITCH * 2;
    const uint32_t bOff = (lr * PITCH + lc) * 2;

    float d[2][8][4];
    #pragma unroll
    for (int at = 0; at < 2; at++)
        #pragma unroll
        for (int nb = 0; nb < 8; nb++)
            #pragma unroll
            for (int q = 0; q < 4; q++) d[at][nb][q] = 0.f;

    // ---------- stage 1 mainloop ----------
    #pragma unroll
    for (int kc = 0; kc < 8; kc++) {
        uint32_t a0h[4], a0l[4], a1h[4], a1l[4];
        ldm4(a0h, aH0 + kc * 32);
        ldm4(a0l, aL0 + kc * 32);
        ldm4(a1h, aH0 + tstride + kc * 32);
        ldm4(a1l, aL0 + tstride + kc * 32);
        #pragma unroll
        for (int g16 = 0; g16 < 4; g16++) {
            uint32_t bh[4], bl[4];
            uint32_t go = (uint32_t)((c0 + g16 * 16) * PITCH * 2) + kc * 32 + bOff;
            ldm4(bh, sb + SM_WH + go);
            ldm4(bl, sb + SM_WL + go);
            mma16816(d[0][2 * g16],     a0h, bh[0], bh[2]);
            mma16816(d[0][2 * g16],     a0l, bh[0], bh[2]);
            mma16816(d[0][2 * g16],     a0h, bl[0], bl[2]);
            mma16816(d[0][2 * g16 + 1], a0h, bh[1], bh[3]);
            mma16816(d[0][2 * g16 + 1], a0l, bh[1], bh[3]);
            mma16816(d[0][2 * g16 + 1], a0h, bl[1], bl[3]);
            mma16816(d[1][2 * g16],     a1h, bh[0], bh[2]);
            mma16816(d[1][2 * g16],     a1l, bh[0], bh[2]);
            mma16816(d[1][2 * g16],     a1h, bl[0], bl[2]);
            mma16816(d[1][2 * g16 + 1], a1h, bh[1], bh[3]);
            mma16816(d[1][2 * g16 + 1], a1l, bh[1], bh[3]);
            mma16816(d[1][2 * g16 + 1], a1h, bl[1], bl[3]);
        }
    }
    __syncthreads();

    const char* wsrc1 = (const char*)g_Wbf + (size_t)(2 * step + 1) * 69632;
    #pragma unroll
    for (int i = 0; i < 17; i++)
        cp16(sb + SM_WH + (i * 256 + tid) * 16, wsrc1 + (i * 256 + tid) * 16);
    cp_commit();

    // epilogue 1: X1 = relu(D + b0) -> split back into Ah/Al
    {
        const int g = lane >> 2, tig = lane & 3;
        uint32_t* hA = (uint32_t*)(smem + SM_AH);
        uint32_t* lA = (uint32_t*)(smem + SM_AL);
        #pragma unroll
        for (int at = 0; at < 2; at++) {
            const int rA = r0 + at * 16 + g, rB = rA + 8;
            #pragma unroll
            for (int nb = 0; nb < 8; nb++) {
                int col = c0 + nb * 8 + tig * 2;
                float bb0 = __ldg(&b0[col]), bb1 = __ldg(&b0[col + 1]);
                float u0 = fmaxf(d[at][nb][0] + bb0, 0.f);
                float u1 = fmaxf(d[at][nb][1] + bb1, 0.f);
                float u2 = fmaxf(d[at][nb][2] + bb0, 0.f);
                float u3 = fmaxf(d[at][nb][3] + bb1, 0.f);
                uint32_t h, l;
                splitpair(u0, u1, h, l);
                hA[(rA * PITCH + col) / 2] = h;
                lA[(rA * PITCH + col) / 2] = l;
                splitpair(u2, u3, h, l);
                hA[(rB * PITCH + col) / 2] = h;
                lA[(rB * PITCH + col) / 2] = l;
                d[at][nb][0] = d[at][nb][1] = d[at][nb][2] = d[at][nb][3] = 0.f;
            }
        }
    }
    cp_wait<0>();
    __syncthreads();

    // ---------- stage 2 mainloop ----------
    #pragma unroll
    for (int kc = 0; kc < 8; kc++) {
        uint32_t a0h[4], a0l[4], a1h[4], a1l[4];
        ldm4(a0h, aH0 + kc * 32);
        ldm4(a0l, aL0 + kc * 32);
        ldm4(a1h, aH0 + tstride + kc * 32);
        ldm4(a1l, aL0 + tstride + kc * 32);
        #pragma unroll
        for (int g16 = 0; g16 < 4; g16++) {
            uint32_t bh[4], bl[4];
            uint32_t go = (uint32_t)((c0 + g16 * 16) * PITCH * 2) + kc * 32 + bOff;
            ldm4(bh, sb + SM_WH + go);
            ldm4(bl, sb + SM_WL + go);
            mma16816(d[0][2 * g16],     a0h, bh[0], bh[2]);
            mma16816(d[0][2 * g16],     a0l, bh[0], bh[2]);
            mma16816(d[0][2 * g16],     a0h, bl[0], bl[2]);
            mma16816(d[0][2 * g16 + 1], a0h, bh[1], bh[3]);
            mma16816(d[0][2 * g16 + 1], a0l, bh[1], bh[3]);
            mma16816(d[0][2 * g16 + 1], a0h, bl[1], bl[3]);
            mma16816(d[1][2 * g16],     a1h, bh[0], bh[2]);
            mma16816(d[1][2 * g16],     a1l, bh[0], bh[2]);
            mma16816(d[1][2 * g16],     a1h, bl[0], bl[2]);
            mma16816(d[1][2 * g16 + 1], a1h, bh[1], bh[3]);
            mma16816(d[1][2 * g16 + 1], a1l, bh[1], bh[3]);
            mma16816(d[1][2 * g16 + 1], a1h, bl[1], bl[3]);
        }
    }

    // epilogue 2: x2 = relu(D + b1) * inv_s -> global fp16
    {
        const int g = lane >> 2, tig = lane & 3;
        #pragma unroll
        for (int at = 0; at < 2; at++) {
            const int rA = r0 + at * 16 + g, rB = rA + 8;
            const float isA = g_inv_s[rowBase + rA];
            const float isB = g_inv_s[rowBase + rB];
            __half* o0 = g_x2 + (rowBase + rA) * 128;
            __half* o1 = g_x2 + (rowBase + rB) * 128;
            #pragma unroll
            for (int nb = 0; nb < 8; nb++) {
                int col = c0 + nb * 8 + tig * 2;
                float bb0 = __ldg(&b1[col]), bb1 = __ldg(&b1[col + 1]);
                float2 vA, vB;
                vA.x = fmaxf(d[at][nb][0] + bb0, 0.f) * isA;
                vA.y = fmaxf(d[at][nb][1] + bb1, 0.f) * isA;
                vB.x = fmaxf(d[at][nb][2] + bb0, 0.f) * isB;
                vB.y = fmaxf(d[at][nb][3] + bb1, 0.f) * isB;
                *(__half2*)(o0 + col) = __float22half2_rn(vA);
                *(__half2*)(o1 + col) = __float22half2_rn(vB);
            }
        }
    }
}

// ---------------- fused aggregate + skip + LayerNorm (+ optional decode) ----
// one warp per node; lane covers 4 features (one uint2 = 2x half2 per edge).
__global__ __launch_bounds__(256) void k_agg_ln(const float* __restrict__ ln_scale,
                                                const float* __restrict__ ln_bias,
                                                const float* __restrict__ Wdec,
                                                const float* __restrict__ bdec,
                                                float* __restrict__ out,
                                                int doDecode) {
    int node = blockIdx.x * 8 + (threadIdx.x >> 5);
    if (node >= N_NODES) return;
    int lane = threadIdx.x & 31;

    const __half2* x2p = (const __half2*)g_x2;

    int b0 = g_off[node], b1 = g_off[node + 1];
    float2 a0 = make_float2(0.f, 0.f), a0b = make_float2(0.f, 0.f);
    float2 a1 = make_float2(0.f, 0.f), a1b = make_float2(0.f, 0.f);
    float2 a2 = make_float2(0.f, 0.f), a2b = make_float2(0.f, 0.f);
    float2 a3 = make_float2(0.f, 0.f), a3b = make_float2(0.f, 0.f);
    int j = b0;
    for (; j + 3 < b1; j += 4) {
        int s0 = g_esrc[j],     s1 = g_esrc[j + 1];
        int s2 = g_esrc[j + 2], s3 = g_esrc[j + 3];
        // 8 bytes per edge per lane: 2 half2 (4 features)
        const __half2* p0 = x2p + (size_t)s0 * 64 + lane * 2;
        const __half2* p1 = x2p + (size_t)s1 * 64 + lane * 2;
        const __half2* p2 = x2p + (size_t)s2 * 64 + lane * 2;
        const __half2* p3 = x2p + (size_t)s3 * 64 + lane * 2;
        __half2 v0a = p0[0], v0b = p0[1];
        __half2 v1a = p1[0], v1b = p1[1];
        __half2 v2a = p2[0], v2b = p2[1];
        __half2 v3a = p3[0], v3b = p3[1];
        float2 f;
        f = __half22float2(v0a); a0.x += f.x; a0.y += f.y;
        f = __half22float2(v0b); a0b.x += f.x; a0b.y += f.y;
        f = __half22float2(v1a); a1.x += f.x; a1.y += f.y;
        f = __half22float2(v1b); a1b.x += f.x; a1b.y += f.y;
        f = __half22float2(v2a); a2.x += f.x; a2.y += f.y;
        f = __half22float2(v2b); a2b.x += f.x; a2b.y += f.y;
        f = __half22float2(v3a); a3.x += f.x; a3.y += f.y;
        f = __half22float2(v3b); a3b.x += f.x; a3b.y += f.y;
    }
    for (; j < b1; j++) {
        int s0 = g_esrc[j];
        const __half2* p0 = x2p + (size_t)s0 * 64 + lane * 2;
        float2 f;
        f = __half22float2(p0[0]); a0.x += f.x; a0.y += f.y;
        f = __half22float2(p0[1]); a0b.x += f.x; a0b.y += f.y;
    }
    float4 acc;
    acc.x = (a0.x + a1.x) + (a2.x + a3.x);
    acc.y = (a0.y + a1.y) + (a2.y + a3.y);
    acc.z = (a0b.x + a1b.x) + (a2b.x + a3b.x);
    acc.w = (a0b.y + a1b.y) + (a2b.y + a3b.y);

    float invr = rsqrtf(fmaxf((float)(b1 - b0), 1.0f));
    float4 hv = *(const float4*)&g_h[(size_t)node * 128 + lane * 4];
    float4 u;
    u.x = fmaf(acc.x, invr, hv.x);
    u.y = fmaf(acc.y, invr, hv.y);
    u.z = fmaf(acc.z, invr, hv.z);
    u.w = fmaf(acc.w, invr, hv.w);

    float sum = u.x + u.y + u.z + u.w;
    float sq  = u.x * u.x + u.y * u.y + u.z * u.z + u.w * u.w;
    #pragma unroll
    for (int d = 16; d > 0; d >>= 1) {
        sum += __shfl_xor_sync(0xFFFFFFFFu, sum, d);
        sq  += __shfl_xor_sync(0xFFFFFFFFu, sq, d);
    }
    float mean = sum * (1.0f / 128.0f);
    float var = sq * (1.0f / 128.0f) - mean * mean;
    float rstd = rsqrtf(var + 1e-6f);

    float4 sc = *(const float4*)&ln_scale[lane * 4];
    float4 bi = *(const float4*)&ln_bias[lane * 4];
    float4 o;
    o.x = (u.x - mean) * rstd * sc.x + bi.x;
    o.y = (u.y - mean) * rstd * sc.y + bi.y;
    o.z = (u.z - mean) * rstd * sc.z + bi.z;
    o.w = (u.w - mean) * rstd * sc.w + bi.w;

    if (!doDecode) {
        *(float4*)&g_h[(size_t)node * 128 + lane * 4] = o;
    } else {
        #pragma unroll
        for (int jj = 0; jj < IN_FEAT; jj++) {
            float p = o.x * __ldg(&Wdec[(lane * 4 + 0) * IN_FEAT + jj])
                    + o.y * __ldg(&Wdec[(lane * 4 + 1) * IN_FEAT + jj])
                    + o.z * __ldg(&Wdec[(lane * 4 + 2) * IN_FEAT + jj])
                    + o.w * __ldg(&Wdec[(lane * 4 + 3) * IN_FEAT + jj]);
            #pragma unroll
            for (int d = 16; d > 0; d >>= 1)
                p += __shfl_xor_sync(0xFFFFFFFFu, p, d);
            if (lane == jj) out[node * IN_FEAT + jj] = p + __ldg(&bdec[jj]);
        }
    }
}

extern "C" void kernel_launch(void* const* d_in, const int* in_sizes, int n_in,
                              void* d_out, int out_size) {
    const float* nodes    = (const float*)d_in[0];
    const int*   senders  = (const int*)  d_in[1];
    const int*   receivers= (const int*)  d_in[2];
    const float* W_embed  = (const float*)d_in[3];
    const float* b_embed  = (const float*)d_in[4];
    const float* mlp_W    = (const float*)d_in[5];
    const float* mlp_b    = (const float*)d_in[6];
    const float* ln_scale = (const float*)d_in[7];
    const float* ln_bias  = (const float*)d_in[8];
    const float* W_dec    = (const float*)d_in[9];
    const float* b_dec    = (const float*)d_in[10];
    float* out = (float*)d_out;

    cudaFuncSetAttribute(k_gemm2bf, cudaFuncAttributeMaxDynamicSharedMemorySize,
                         SM_TOT);

    const int GEMM_GRID = N_PAD / 128;   // 391

    // inv_s must exist before the first GEMM (epilogue folds it in)
    k_zero   <<<(N_NODES + 255) / 256, 256>>>();
    k_count  <<<(N_EDGES + 255) / 256, 256>>>(senders, receivers);
    k_wsplit6<<<(6 * 16384 + 255) / 256, 256>>>(mlp_W);
    k_embed  <<<(N_NODES * LATENT + 255) / 256, 256>>>(nodes, W_embed, b_embed);
    k_scan_all<<<1, 1024>>>();
    k_fill   <<<(N_EDGES + 255) / 256, 256>>>(senders, receivers);

    for (int step = 0; step < STEPS; step++) {
        k_gemm2bf<<<GEMM_GRID, 256, SM_TOT>>>(step,
                                              mlp_b + step * 256,
                                              mlp_b + step * 256 + 128);
        k_agg_ln<<<(N_NODES + 7) / 8, 256>>>(ln_scale + step * LATENT,
                                             ln_bias + step * LATENT,
                                             W_dec, b_dec, out,
                                             step == STEPS - 1 ? 1 : 0);
    }
}

// round 16
// speedup vs baseline: 2.1730x; 1.0408x over previous
#include <cuda_runtime.h>
#include <cuda_bf16.h>
#include <cuda_fp16.h>
#include <cstdint>

#define N_NODES 50000
#define N_PAD   50048            // 391 * 128
#define N_EDGES 600000
#define LATENT 128
#define IN_FEAT 7
#define STEPS 3

// -------- scratch (static device globals; zero-initialized) --------
__device__ float  g_h [N_PAD * LATENT];
__device__ __half g_x2[N_PAD * LATENT];          // fp16 messages (scaled by inv_s)
__device__ float  g_inv_s[N_PAD];
__device__ int    g_cnt_s[N_NODES];
__device__ int    g_cnt_r[N_NODES];
__device__ int    g_off  [N_NODES + 1];
__device__ int    g_cursor[N_NODES];
__device__ int    g_esrc [N_EDGES];
// pre-split weights, [mat][hi 128x136][lo 128x136] bf16, row = n, col = k
__device__ __align__(16) __nv_bfloat16 g_Wbf[6 * 2 * 128 * 136];

// ---------------- helpers ----------------
__device__ __forceinline__ void cp16(uint32_t dst, const void* src) {
    asm volatile("cp.async.ca.shared.global [%0], [%1], 16;" :: "r"(dst), "l"(src));
}
__device__ __forceinline__ void cp_commit() {
    asm volatile("cp.async.commit_group;");
}
template <int N>
__device__ __forceinline__ void cp_wait() {
    asm volatile("cp.async.wait_group %0;" :: "n"(N));
}
__device__ __forceinline__ uint32_t pack_bf(float lo, float hi) {
    uint32_t r;
    asm("cvt.rn.bf16x2.f32 %0, %1, %2;" : "=r"(r) : "f"(hi), "f"(lo));
    return r;
}
__device__ __forceinline__ void splitpair(float c0, float c1,
                                          uint32_t& h, uint32_t& l) {
    h = pack_bf(c0, c1);
    float h0 = __uint_as_float(h << 16);
    float h1 = __uint_as_float(h & 0xffff0000u);
    l = pack_bf(c0 - h0, c1 - h1);
}
__device__ __forceinline__ void ldm4(uint32_t* r, uint32_t addr) {
    asm volatile("ldmatrix.sync.aligned.m8n8.x4.shared.b16 {%0,%1,%2,%3}, [%4];"
                 : "=r"(r[0]), "=r"(r[1]), "=r"(r[2]), "=r"(r[3]) : "r"(addr));
}
__device__ __forceinline__ void mma16816(float* d, const uint32_t* a,
                                         uint32_t b0, uint32_t b1) {
    asm volatile(
        "mma.sync.aligned.m16n8k16.row.col.f32.bf16.bf16.f32 "
        "{%0,%1,%2,%3}, {%4,%5,%6,%7}, {%8,%9}, {%0,%1,%2,%3};"
        : "+f"(d[0]), "+f"(d[1]), "+f"(d[2]), "+f"(d[3])
        : "r"(a[0]), "r"(a[1]), "r"(a[2]), "r"(a[3]), "r"(b0), "r"(b1));
}

// ---------------- prologue ----------------
__global__ void k_zero() {
    int i = blockIdx.x * blockDim.x + threadIdx.x;
    if (i < N_NODES) { g_cnt_s[i] = 0; g_cnt_r[i] = 0; }
}

__global__ void k_count(const int* __restrict__ snd, const int* __restrict__ rcv) {
    int e = blockIdx.x * blockDim.x + threadIdx.x;
    if (e < N_EDGES) {
        atomicAdd(&g_cnt_s[snd[e]], 1);
        atomicAdd(&g_cnt_r[rcv[e]], 1);
    }
}

__global__ __launch_bounds__(1024) void k_scan_all() {
    __shared__ int warp_sums[32];
    const int t = threadIdx.x;
    const int lane = t & 31;
    const int wid = t >> 5;
    int base = 0;

    const int NT = (N_NODES + 1023) / 1024;
    for (int j = 0; j < NT; j++) {
        int i = j * 1024 + t;
        int v = (i < N_NODES) ? g_cnt_r[i] : 0;
        int x = v;
        #pragma unroll
        for (int d = 1; d < 32; d <<= 1) {
            int y = __shfl_up_sync(0xFFFFFFFFu, x, d);
            if (lane >= d) x += y;
        }
        if (lane == 31) warp_sums[wid] = x;
        __syncthreads();
        if (t < 32) {
            int y = warp_sums[t];
            #pragma unroll
            for (int d = 1; d < 32; d <<= 1) {
                int z = __shfl_up_sync(0xFFFFFFFFu, y, d);
                if (t >= d) y += z;
            }
            warp_sums[t] = y;
        }
        __syncthreads();
        int incl = x + (wid ? warp_sums[wid - 1] : 0);
        int total = warp_sums[31];
        int excl = base + incl - v;
        if (i < N_NODES) {
            g_off[i] = excl;
            g_cursor[i] = excl;
            g_inv_s[i] = rsqrtf(fmaxf((float)g_cnt_s[i], 1.0f));
        }
        base += total;
        __syncthreads();
    }
    if (t == 0) g_off[N_NODES] = N_EDGES;
}

__global__ void k_fill(const int* __restrict__ snd, const int* __restrict__ rcv) {
    int e = blockIdx.x * blockDim.x + threadIdx.x;
    if (e < N_EDGES) {
        int r = rcv[e];
        int pos = atomicAdd(&g_cursor[r], 1);
        g_esrc[pos] = snd[e];
    }
}

// ---------------- weight pre-split: W[k][n] fp32 -> [n][k] bf16 hi/lo ------
__global__ void k_wsplit6(const float* __restrict__ mlpW) {
    int i = blockIdx.x * blockDim.x + threadIdx.x;
    if (i >= 6 * 16384) return;
    int mat = i >> 14;
    int rem = i & 16383;
    int n = rem >> 7;
    int k = rem & 127;
    float wv = mlpW[(size_t)mat * 16384 + k * 128 + n];
    __nv_bfloat16 h = __float2bfloat16(wv);
    float fh = __bfloat162float(h);
    __nv_bfloat16 l = __float2bfloat16(wv - fh);
    size_t base = (size_t)mat * 34816 + n * 136 + k;
    g_Wbf[base] = h;
    g_Wbf[base + 17408] = l;
}

// ---------------- embed: warp per node, shfl-broadcast inputs ----------------
__global__ __launch_bounds__(256) void k_embed(const float* __restrict__ nodes,
                                               const float* __restrict__ Wemb,
                                               const float* __restrict__ bemb) {
    int node = blockIdx.x * 8 + (threadIdx.x >> 5);
    if (node >= N_NODES) return;
    int lane = threadIdx.x & 31;

    float v = (lane < IN_FEAT) ? __ldg(&nodes[node * IN_FEAT + lane]) : 0.f;
    float f[IN_FEAT];
    #pragma unroll
    for (int k = 0; k < IN_FEAT; k++)
        f[k] = __shfl_sync(0xFFFFFFFFu, v, k);

    int col = lane * 4;
    float4 acc = *(const float4*)&bemb[col];
    #pragma unroll
    for (int k = 0; k < IN_FEAT; k++) {
        float4 wv = __ldg((const float4*)&Wemb[k * 128 + col]);
        acc.x = fmaf(f[k], wv.x, acc.x);
        acc.y = fmaf(f[k], wv.y, acc.y);
        acc.z = fmaf(f[k], wv.z, acc.z);
        acc.w = fmaf(f[k], wv.w, acc.w);
    }
    *(float4*)&g_h[(size_t)node * 128 + col] = acc;
}

// ---------------- fused dual GEMM on bf16 mma.sync (split hi/lo) ----------
// x2 = relu( relu(h@W0+b0) @ W1 + b1 ) * inv_s[row], stored as fp16.
// MMA issue order is PRODUCT-MAJOR: 4 independent accumulators between
// reuses of the same accumulator (asm volatile blocks ptxas reordering).
#define PITCH 136
#define SM_AH 0
#define SM_AL 34816
#define SM_WH 69632
#define SM_WL 104448
#define SM_TOT 139264

#define MMA_GROUP(AH0, AL0, A1H, A1L, BH, BL, D0a, D0b, D1a, D1b)   \
    do {                                                            \
        mma16816(D0a, AH0, BH[0], BH[2]);                           \
        mma16816(D0b, AH0, BH[1], BH[3]);                           \
        mma16816(D1a, A1H, BH[0], BH[2]);                           \
        mma16816(D1b, A1H, BH[1], BH[3]);                           \
        mma16816(D0a, AL0, BH[0], BH[2]);                           \
        mma16816(D0b, AL0, BH[1], BH[3]);                           \
        mma16816(D1a, A1L, BH[0], BH[2]);                           \
        mma16816(D1b, A1L, BH[1], BH[3]);                           \
        mma16816(D0a, AH0, BL[0], BL[2]);                           \
        mma16816(D0b, AH0, BL[1], BL[3]);                           \
        mma16816(D1a, A1H, BL[0], BL[2]);                           \
        mma16816(D1b, A1H, BL[1], BL[3]);                           \
    } while (0)

__global__ __launch_bounds__(256) void k_gemm2bf(int step,
                                                 const float* __restrict__ b0,
                                                 const float* __restrict__ b1) {
    extern __shared__ __align__(16) unsigned char smem[];
    const uint32_t sb = (uint32_t)__cvta_generic_to_shared(smem);
    const int tid = threadIdx.x;
    const int lane = tid & 31;
    const int w = tid >> 5;
    const size_t rowBase = (size_t)blockIdx.x * 128;

    const char* wsrc0 = (const char*)g_Wbf + (size_t)(2 * step) * 69632;
    #pragma unroll
    for (int i = 0; i < 17; i++)
        cp16(sb + SM_WH + (i * 256 + tid) * 16, wsrc0 + (i * 256 + tid) * 16);
    cp_commit();

    // convert A rows to bf16 hi/lo while W0 streams (thread = half row)
    {
        int row = tid >> 1;
        int cbase = (tid & 1) * 64;
        const float* src = g_h + (rowBase + row) * 128 + cbase;
        uint32_t* dh = (uint32_t*)(smem + SM_AH) + (row * PITCH + cbase) / 2;
        uint32_t* dl = (uint32_t*)(smem + SM_AL) + (row * PITCH + cbase) / 2;
        #pragma unroll
        for (int i = 0; i < 16; i++) {
            float4 v = *(const float4*)(src + i * 4);
            uint32_t h0, l0, h1, l1;
            splitpair(v.x, v.y, h0, l0);
            splitpair(v.z, v.w, h1, l1);
            dh[i * 2]     = h0; dh[i * 2 + 1] = h1;
            dl[i * 2]     = l0; dl[i * 2 + 1] = l1;
        }
    }
    cp_wait<0>();
    __syncthreads();

    const int r0 = (w >> 1) * 32;
    const int c0 = (w & 1) * 64;
    const int lr = (lane & 7) + ((lane >> 3) & 1) * 8;
    const int lc = (lane >> 4) * 8;
    const uint32_t aH0 = sb + SM_AH + ((r0 + lr) * PITCH + lc) * 2;
    const uint32_t aL0 = sb + SM_AL + ((r0 + lr) * PITCH + lc) * 2;
    const uint32_t tstride = 16 * PITCH * 2;
    const uint32_t bOff = (lr * PITCH + lc) * 2;

    float d[2][8][4];
    #pragma unroll
    for (int at = 0; at < 2; at++)
        #pragma unroll
        for (int nb = 0; nb < 8; nb++)
            #pragma unroll
            for (int q = 0; q < 4; q++) d[at][nb][q] = 0.f;

    // ---------- stage 1 mainloop ----------
    #pragma unroll
    for (int kc = 0; kc < 8; kc++) {
        uint32_t a0h[4], a0l[4], a1h[4], a1l[4];
        ldm4(a0h, aH0 + kc * 32);
        ldm4(a0l, aL0 + kc * 32);
        ldm4(a1h, aH0 + tstride + kc * 32);
        ldm4(a1l, aL0 + tstride + kc * 32);
        #pragma unroll
        for (int g16 = 0; g16 < 4; g16++) {
            uint32_t bh[4], bl[4];
            uint32_t go = (uint32_t)((c0 + g16 * 16) * PITCH * 2) + kc * 32 + bOff;
            ldm4(bh, sb + SM_WH + go);
            ldm4(bl, sb + SM_WL + go);
            MMA_GROUP(a0h, a0l, a1h, a1l, bh, bl,
                      d[0][2 * g16], d[0][2 * g16 + 1],
                      d[1][2 * g16], d[1][2 * g16 + 1]);
        }
    }
    __syncthreads();

    const char* wsrc1 = (const char*)g_Wbf + (size_t)(2 * step + 1) * 69632;
    #pragma unroll
    for (int i = 0; i < 17; i++)
        cp16(sb + SM_WH + (i * 256 + tid) * 16, wsrc1 + (i * 256 + tid) * 16);
    cp_commit();

    // epilogue 1: X1 = relu(D + b0) -> split back into Ah/Al
    {
        const int g = lane >> 2, tig = lane & 3;
        uint32_t* hA = (uint32_t*)(smem + SM_AH);
        uint32_t* lA = (uint32_t*)(smem + SM_AL);
        #pragma unroll
        for (int at = 0; at < 2; at++) {
            const int rA = r0 + at * 16 + g, rB = rA + 8;
            #pragma unroll
            for (int nb = 0; nb < 8; nb++) {
                int col = c0 + nb * 8 + tig * 2;
                float bb0 = __ldg(&b0[col]), bb1 = __ldg(&b0[col + 1]);
                float u0 = fmaxf(d[at][nb][0] + bb0, 0.f);
                float u1 = fmaxf(d[at][nb][1] + bb1, 0.f);
                float u2 = fmaxf(d[at][nb][2] + bb0, 0.f);
                float u3 = fmaxf(d[at][nb][3] + bb1, 0.f);
                uint32_t h, l;
                splitpair(u0, u1, h, l);
                hA[(rA * PITCH + col) / 2] = h;
                lA[(rA * PITCH + col) / 2] = l;
                splitpair(u2, u3, h, l);
                hA[(rB * PITCH + col) / 2] = h;
                lA[(rB * PITCH + col) / 2] = l;
                d[at][nb][0] = d[at][nb][1] = d[at][nb][2] = d[at][nb][3] = 0.f;
            }
        }
    }
    cp_wait<0>();
    __syncthreads();

    // ---------- stage 2 mainloop ----------
    #pragma unroll
    for (int kc = 0; kc < 8; kc++) {
        uint32_t a0h[4], a0l[4], a1h[4], a1l[4];
        ldm4(a0h, aH0 + kc * 32);
        ldm4(a0l, aL0 + kc * 32);
        ldm4(a1h, aH0 + tstride + kc * 32);
        ldm4(a1l, aL0 + tstride + kc * 32);
        #pragma unroll
        for (int g16 = 0; g16 < 4; g16++) {
            uint32_t bh[4], bl[4];
            uint32_t go = (uint32_t)((c0 + g16 * 16) * PITCH * 2) + kc * 32 + bOff;
            ldm4(bh, sb + SM_WH + go);
            ldm4(bl, sb + SM_WL + go);
            MMA_GROUP(a0h, a0l, a1h, a1l, bh, bl,
                      d[0][2 * g16], d[0][2 * g16 + 1],
                      d[1][2 * g16], d[1][2 * g16 + 1]);
        }
    }

    // epilogue 2: x2 = relu(D + b1) * inv_s -> global fp16
    {
        const int g = lane >> 2, tig = lane & 3;
        #pragma unroll
        for (int at = 0; at < 2; at++) {
            const int rA = r0 + at * 16 + g, rB = rA + 8;
            const float isA = g_inv_s[rowBase + rA];
            const float isB = g_inv_s[rowBase + rB];
            __half* o0 = g_x2 + (rowBase + rA) * 128;
            __half* o1 = g_x2 + (rowBase + rB) * 128;
            #pragma unroll
            for (int nb = 0; nb < 8; nb++) {
                int col = c0 + nb * 8 + tig * 2;
                float bb0 = __ldg(&b1[col]), bb1 = __ldg(&b1[col + 1]);
                float2 vA, vB;
                vA.x = fmaxf(d[at][nb][0] + bb0, 0.f) * isA;
                vA.y = fmaxf(d[at][nb][1] + bb1, 0.f) * isA;
                vB.x = fmaxf(d[at][nb][2] + bb0, 0.f) * isB;
                vB.y = fmaxf(d[at][nb][3] + bb1, 0.f) * isB;
                *(__half2*)(o0 + col) = __float22half2_rn(vA);
                *(__half2*)(o1 + col) = __float22half2_rn(vB);
            }
        }
    }
}

// ---------------- fused aggregate + skip + LayerNorm (+ optional decode) ----
__global__ __launch_bounds__(256) void k_agg_ln(const float* __restrict__ ln_scale,
                                                const float* __restrict__ ln_bias,
                                                const float* __restrict__ Wdec,
                                                const float* __restrict__ bdec,
                                                float* __restrict__ out,
                                                int doDecode) {
    int node = blockIdx.x * 8 + (threadIdx.x >> 5);
    if (node >= N_NODES) return;
    int lane = threadIdx.x & 31;

    const __half2* x2p = (const __half2*)g_x2;

    int b0 = g_off[node], b1 = g_off[node + 1];
    float2 a0 = make_float2(0.f, 0.f), a0b = make_float2(0.f, 0.f);
    float2 a1 = make_float2(0.f, 0.f), a1b = make_float2(0.f, 0.f);
    float2 a2 = make_float2(0.f, 0.f), a2b = make_float2(0.f, 0.f);
    float2 a3 = make_float2(0.f, 0.f), a3b = make_float2(0.f, 0.f);
    int j = b0;
    for (; j + 3 < b1; j += 4) {
        int s0 = g_esrc[j],     s1 = g_esrc[j + 1];
        int s2 = g_esrc[j + 2], s3 = g_esrc[j + 3];
        const __half2* p0 = x2p + (size_t)s0 * 64 + lane * 2;
        const __half2* p1 = x2p + (size_t)s1 * 64 + lane * 2;
        const __half2* p2 = x2p + (size_t)s2 * 64 + lane * 2;
        const __half2* p3 = x2p + (size_t)s3 * 64 + lane * 2;
        __half2 v0a = p0[0], v0b = p0[1];
        __half2 v1a = p1[0], v1b = p1[1];
        __half2 v2a = p2[0], v2b = p2[1];
        __half2 v3a = p3[0], v3b = p3[1];
        float2 f;
        f = __half22float2(v0a); a0.x += f.x; a0.y += f.y;
        f = __half22float2(v0b); a0b.x += f.x; a0b.y += f.y;
        f = __half22float2(v1a); a1.x += f.x; a1.y += f.y;
        f = __half22float2(v1b); a1b.x += f.x; a1b.y += f.y;
        f = __half22float2(v2a); a2.x += f.x; a2.y += f.y;
        f = __half22float2(v2b); a2b.x += f.x; a2b.y += f.y;
        f = __half22float2(v3a); a3.x += f.x; a3.y += f.y;
        f = __half22float2(v3b); a3b.x += f.x; a3b.y += f.y;
    }
    for (; j < b1; j++) {
        int s0 = g_esrc[j];
        const __half2* p0 = x2p + (size_t)s0 * 64 + lane * 2;
        float2 f;
        f = __half22float2(p0[0]); a0.x += f.x; a0.y += f.y;
        f = __half22float2(p0[1]); a0b.x += f.x; a0b.y += f.y;
    }
    float4 acc;
    acc.x = (a0.x + a1.x) + (a2.x + a3.x);
    acc.y = (a0.y + a1.y) + (a2.y + a3.y);
    acc.z = (a0b.x + a1b.x) + (a2b.x + a3b.x);
    acc.w = (a0b.y + a1b.y) + (a2b.y + a3b.y);

    float invr = rsqrtf(fmaxf((float)(b1 - b0), 1.0f));
    float4 hv = *(const float4*)&g_h[(size_t)node * 128 + lane * 4];
    float4 u;
    u.x = fmaf(acc.x, invr, hv.x);
    u.y = fmaf(acc.y, invr, hv.y);
    u.z = fmaf(acc.z, invr, hv.z);
    u.w = fmaf(acc.w, invr, hv.w);

    float sum = u.x + u.y + u.z + u.w;
    float sq  = u.x * u.x + u.y * u.y + u.z * u.z + u.w * u.w;
    #pragma unroll
    for (int d = 16; d > 0; d >>= 1) {
        sum += __shfl_xor_sync(0xFFFFFFFFu, sum, d);
        sq  += __shfl_xor_sync(0xFFFFFFFFu, sq, d);
    }
    float mean = sum * (1.0f / 128.0f);
    float var = sq * (1.0f / 128.0f) - mean * mean;
    float rstd = rsqrtf(var + 1e-6f);

    float4 sc = *(const float4*)&ln_scale[lane * 4];
    float4 bi = *(const float4*)&ln_bias[lane * 4];
    float4 o;
    o.x = (u.x - mean) * rstd * sc.x + bi.x;
    o.y = (u.y - mean) * rstd * sc.y + bi.y;
    o.z = (u.z - mean) * rstd * sc.z + bi.z;
    o.w = (u.w - mean) * rstd * sc.w + bi.w;

    if (!doDecode) {
        *(float4*)&g_h[(size_t)node * 128 + lane * 4] = o;
    } else {
        #pragma unroll
        for (int jj = 0; jj < IN_FEAT; jj++) {
            float p = o.x * __ldg(&Wdec[(lane * 4 + 0) * IN_FEAT + jj])
                    + o.y * __ldg(&Wdec[(lane * 4 + 1) * IN_FEAT + jj])
                    + o.z * __ldg(&Wdec[(lane * 4 + 2) * IN_FEAT + jj])
                    + o.w * __ldg(&Wdec[(lane * 4 + 3) * IN_FEAT + jj]);
            #pragma unroll
            for (int d = 16; d > 0; d >>= 1)
                p += __shfl_xor_sync(0xFFFFFFFFu, p, d);
            if (lane == jj) out[node * IN_FEAT + jj] = p + __ldg(&bdec[jj]);
        }
    }
}

extern "C" void kernel_launch(void* const* d_in, const int* in_sizes, int n_in,
                              void* d_out, int out_size) {
    const float* nodes    = (const float*)d_in[0];
    const int*   senders  = (const int*)  d_in[1];
    const int*   receivers= (const int*)  d_in[2];
    const float* W_embed  = (const float*)d_in[3];
    const float* b_embed  = (const float*)d_in[4];
    const float* mlp_W    = (const float*)d_in[5];
    const float* mlp_b    = (const float*)d_in[6];
    const float* ln_scale = (const float*)d_in[7];
    const float* ln_bias  = (const float*)d_in[8];
    const float* W_dec    = (const float*)d_in[9];
    const float* b_dec    = (const float*)d_in[10];
    float* out = (float*)d_out;

    cudaFuncSetAttribute(k_gemm2bf, cudaFuncAttributeMaxDynamicSharedMemorySize,
                         SM_TOT);

    const int GEMM_GRID = N_PAD / 128;   // 391

    k_zero   <<<(N_NODES + 255) / 256, 256>>>();
    k_count  <<<(N_EDGES + 255) / 256, 256>>>(senders, receivers);
    k_wsplit6<<<(6 * 16384 + 255) / 256, 256>>>(mlp_W);
    k_embed  <<<(N_NODES + 7) / 8, 256>>>(nodes, W_embed, b_embed);
    k_scan_all<<<1, 1024>>>();
    k_fill   <<<(N_EDGES + 255) / 256, 256>>>(senders, receivers);

    for (int step = 0; step < STEPS; step++) {
        k_gemm2bf<<<GEMM_GRID, 256, SM_TOT>>>(step,
                                              mlp_b + step * 256,
                                              mlp_b + step * 256 + 128);
        k_agg_ln<<<(N_NODES + 7) / 8, 256>>>(ln_scale + step * LATENT,
                                             ln_bias + step * LATENT,
                                             W_dec, b_dec, out,
                                             step == STEPS - 1 ? 1 : 0);
    }
}